// round 14
// baseline (speedup 1.0000x reference)
#include <cuda_runtime.h>
#include <cstdint>
#include <cmath>

#define CB 8192
#define NNODES 25
// group sizes: 25, 9, 7, 6, 6

__constant__ int GIDX[5][25] = {
  {0,1,2,3,4,5,6,7,8,9,10,11,12,13,14,15,16,17,18,19,20,21,22,23,24},
  {0,1,2,3,4,5,6,7,8, 0,0,0,0,0,0,0,0,0,0,0,0,0,0,0,0},
  {0,9,10,11,12,13,14, 0,0,0,0,0,0,0,0,0,0,0,0,0,0,0,0,0,0},
  {6,7,8,12,13,14, 0,0,0,0,0,0,0,0,0,0,0,0,0,0,0,0,0,0,0},
  {3,4,5,9,10,11, 0,0,0,0,0,0,0,0,0,0,0,0,0,0,0,0,0,0,0}
};

// device scratch (no allocations allowed)
__device__ float g_h  [(size_t)CB * 53 * 512];  // h = relu(xa@W1+b1), tf32-rounded
__device__ float g_xa [(size_t)CB * 53 * 256];  // xa = NA@x (tf32-rounded)
__device__ float g_nat[(size_t)CB * 1096];      // NA, padded, j-major per group
__device__ float g_W1r[5 * 512 * 256];          // W1^T: [g][n][k], tf32-rounded
__device__ float g_W2r[5 * 256 * 512];          // W2^T: [g][n][k], tf32-rounded

__host__ __device__ constexpr size_t hpre(int g) {
    return g == 0 ? 0 : g == 1 ? 25 : g == 2 ? 34 : g == 3 ? 41 : 47;
}
__host__ __device__ constexpr int natoff(int g) {
    return g == 0 ? 0 : g == 1 ? 800 : g == 2 ? 944 : g == 3 ? 1000 : 1048;
}

__device__ __forceinline__ uint32_t smem_u32(const void* p) {
    uint32_t a;
    asm("{ .reg .u64 t; cvta.to.shared.u64 t, %1; cvt.u32.u64 %0, t; }"
        : "=r"(a) : "l"(p));
    return a;
}
__device__ __forceinline__ float tf32r(float v) {
    uint32_t o;
    asm("cvt.rna.tf32.f32 %0, %1;" : "=r"(o) : "f"(v));
    return __uint_as_float(o);
}
__device__ __forceinline__ void cp16(uint32_t dst, const void* src) {
    asm volatile("cp.async.cg.shared.global [%0], [%1], 16;"
                 :: "r"(dst), "l"(src) : "memory");
}
__device__ __forceinline__ void cp_commit() {
    asm volatile("cp.async.commit_group;" ::: "memory");
}
__device__ __forceinline__ void cp_wait1() {
    asm volatile("cp.async.wait_group 1;" ::: "memory");
}
__device__ __forceinline__ void ldsm4(uint32_t* r, uint32_t addr) {
    asm volatile("ldmatrix.sync.aligned.m8n8.x4.shared.b16 {%0,%1,%2,%3}, [%4];"
        : "=r"(r[0]), "=r"(r[1]), "=r"(r[2]), "=r"(r[3]) : "r"(addr));
}
__device__ __forceinline__ void mma_tf32(float* d, const uint32_t* a, const uint32_t* b) {
    asm volatile(
        "mma.sync.aligned.m16n8k8.row.col.f32.tf32.tf32.f32 "
        "{%0,%1,%2,%3}, {%4,%5,%6,%7}, {%8,%9}, {%0,%1,%2,%3};"
        : "+f"(d[0]), "+f"(d[1]), "+f"(d[2]), "+f"(d[3])
        : "r"(a[0]), "r"(a[1]), "r"(a[2]), "r"(a[3]), "r"(b[0]), "r"(b[1]));
}
__device__ __forceinline__ uint64_t packf2(float v) {
    uint64_t d;
    asm("mov.b64 %0, {%1, %1};" : "=l"(d) : "r"(__float_as_uint(v)));
    return d;
}
__device__ __forceinline__ void fmaf2(uint64_t& o, uint64_t a, uint64_t b) {
    asm("fma.rn.f32x2 %0, %1, %2, %0;" : "+l"(o) : "l"(a), "l"(b));
}

// ---------------------------------------------------------------------------
// Weight pre-pass: transpose to [g][n][k] + tf32-round.
// ---------------------------------------------------------------------------
__global__ void wround(const float* __restrict__ W1, const float* __restrict__ W2) {
    const int t = blockIdx.x * 256 + threadIdx.x;
    if (t < 5 * 512 * 256) {
        const int g = t / (512 * 256), r = t - g * 512 * 256;
        const int n = r >> 8, k = r & 255;
        g_W1r[t] = tf32r(W1[(size_t)(g * 256 + k) * 512 + n]);
    }
    if (t < 5 * 256 * 512) {
        const int g = t / (256 * 512), r = t - g * 256 * 512;
        const int n = r >> 9, k = r & 511;
        g_W2r[t] = tf32r(W2[(size_t)(g * 512 + k) * 256 + n]);
    }
}

// ---------------------------------------------------------------------------
// Pre-pass: per batch, NA per group (padded j-major) and xa = NA @ x.
// ---------------------------------------------------------------------------
template<int G, int GN, int GNP>
__device__ void aggx_group(int b, int tid, const float* xs, const float* adjs,
                           float* na_s, float* dinv) {
    if (tid < GN) {
        float deg = 1.f;
#pragma unroll
        for (int j = 0; j < GN; ++j)
            deg += adjs[GIDX[G][tid] * 25 + GIDX[G][j]];
        dinv[tid] = rsqrtf(deg);
    }
    __syncthreads();
    for (int e = tid; e < GN * GN; e += 256) {
        const int i = e / GN, j = e - i * GN;
        float v = adjs[GIDX[G][i] * 25 + GIDX[G][j]] + (i == j ? 1.f : 0.f);
        na_s[e] = v * dinv[i] * dinv[j];
    }
    __syncthreads();
    float* natd = g_nat + (size_t)b * 1096 + natoff(G);
    for (int e = tid; e < GN * GNP; e += 256) {
        const int j = e / GNP, i = e - j * GNP;
        natd[e] = (i < GN) ? na_s[i * GN + j] : 0.f;
    }
    float* xad = g_xa + hpre(G) * (size_t)CB * 256 + (size_t)b * GN * 256;
    for (int u = tid; u < GN * 64; u += 256) {
        const int i = u >> 6, c = (u & 63) * 4;
        float4 o = make_float4(0.f, 0.f, 0.f, 0.f);
#pragma unroll
        for (int j = 0; j < GN; ++j) {
            const float na = na_s[i * GN + j];
            const float4 xv = *(const float4*)&xs[GIDX[G][j] * 260 + c];
            o.x += na * xv.x; o.y += na * xv.y;
            o.z += na * xv.z; o.w += na * xv.w;
        }
        o.x = tf32r(o.x); o.y = tf32r(o.y); o.z = tf32r(o.z); o.w = tf32r(o.w);
        *(float4*)&xad[i * 256 + c] = o;
    }
    __syncthreads();
}

__global__ __launch_bounds__(256)
void aggx(const float* __restrict__ x, const float* __restrict__ adj) {
    __shared__ float xs[25 * 260];
    __shared__ float adjs[625];
    __shared__ float na_s[625];
    __shared__ float dinv[25];
    const int b = blockIdx.x, tid = threadIdx.x;
    for (int e = tid; e < 25 * 256; e += 256) {
        const int row = e >> 8, col = e & 255;
        xs[row * 260 + col] = x[(size_t)b * 6400 + e];
    }
    for (int e = tid; e < 625; e += 256) adjs[e] = adj[(size_t)b * 625 + e];
    __syncthreads();
    aggx_group<0, 25, 32>(b, tid, xs, adjs, na_s, dinv);
    aggx_group<1,  9, 16>(b, tid, xs, adjs, na_s, dinv);
    aggx_group<2,  7,  8>(b, tid, xs, adjs, na_s, dinv);
    aggx_group<3,  6,  8>(b, tid, xs, adjs, na_s, dinv);
    aggx_group<4,  6,  8>(b, tid, xs, adjs, na_s, dinv);
}

// KC=32 chunk, 3-stage ring. A and B both [128 rows][32f], stride 36f
// (conflict-free LDSM: row offsets {0,16,...,112} mod 128).
#define SA_B   (128 * 36 * 4)      // 18432
#define SB_B   (128 * 36 * 4)      // 18432
#define STAGEB (SA_B + SB_B)       // 36864
#define STAGE3 (3 * STAGEB)        // 110592 (x2 CTA = 221184 <= 228KB)
#define NAT_SOFF 67584             // NAt epilogue home, above S[128][132]

// ---------------------------------------------------------------------------
// Layer 1: h = relu(xa @ W1 + b1) -> g_h (tf32-rounded). Pure GEMM.
// Grid: x = n-tile (fast), y = batch-block, z = group offset.
// ---------------------------------------------------------------------------
template<int GN, int BB>
__global__ __launch_bounds__(256, 2)
void gcn_l1(const float* __restrict__ b1, int gbase)
{
    constexpr int K     = 256;
    constexpr int KC    = 32;
    constexpr int NC    = K / KC;      // 8
    constexpr int MROWS = BB * GN;

    extern __shared__ char smem[];
    float* smf = (float*)smem;
    const uint32_t sb = smem_u32(smem);

    const int tid  = threadIdx.x;
    const int lane = tid & 31;
    const int wid  = tid >> 5;
    const int warpM = wid >> 2;
    const int warpN = wid & 3;
    const int G      = gbase + blockIdx.z;
    const int n0     = blockIdx.x * 128;
    const int batch0 = blockIdx.y * BB;

    const float* Asrc = g_xa + hpre(G) * (size_t)CB * 256;
    const float* Bsrc = g_W1r + (size_t)G * 512 * 256;   // [n][k]
    const float* bias = b1 + G * 512;
    float* hdst = g_h + hpre(G) * (size_t)CB * 512;

    const float* aSrc[4]; uint32_t aDst[4];
    const float* bSrc[4]; uint32_t bDst[4];
#pragma unroll
    for (int i = 0; i < 4; ++i) {
        const int idx = i * 256 + tid;        // 0..1023
        const int row = idx >> 3, kq = idx & 7;
        const bool valid = (row < MROWS) && (batch0 + row / GN < CB);
        aSrc[i] = (valid ? Asrc + (size_t)(batch0 * GN + row) * 256 : Asrc) + kq * 4;
        aDst[i] = row * 144 + kq * 16;
        bSrc[i] = Bsrc + (size_t)(n0 + row) * K + kq * 4;
        bDst[i] = SA_B + row * 144 + kq * 16;
    }
    auto stage = [&](int c, int p) {
        const uint32_t base = sb + p * STAGEB;
#pragma unroll
        for (int i = 0; i < 4; ++i) cp16(base + aDst[i], aSrc[i] + c * KC);
#pragma unroll
        for (int i = 0; i < 4; ++i) cp16(base + bDst[i], bSrc[i] + c * KC);
    };

    float acc[4][4][4];
#pragma unroll
    for (int mt = 0; mt < 4; ++mt)
#pragma unroll
        for (int nt = 0; nt < 4; ++nt)
#pragma unroll
            for (int r = 0; r < 4; ++r) acc[mt][nt][r] = 0.f;

    stage(0, 0); cp_commit();
    stage(1, 1); cp_commit();

    float2 bs[4];
#pragma unroll
    for (int nt = 0; nt < 4; ++nt)
        bs[nt] = *(const float2*)&bias[n0 + warpN * 32 + nt * 8 + (lane & 3) * 2];

    // A ldmatrix: lanes 0-7 rows r0-7 (m0), 8-15 rows r8-15 (m1),
    //             16-23 rows r0-7 k+4 (m2), 24-31 rows r8-15 k+4 (m3)
    const uint32_t lmA =
        ((warpM * 64 + (lane & 7) + ((lane >> 3) & 1) * 8) * 36 +
         (lane >> 4) * 4) * 4;
    // B ldmatrix: lanes 0-7 rows n0-7 k+0 (m0), 8-15 same rows k+4 (m1),
    //             16-23 rows n0-7 k+8 (m2), 24-31 same rows k+12 (m3)
    //   -> regs r0,r1 = b[kc even], r2,r3 = b[kc odd]
    const uint32_t lmB = SA_B +
        ((warpN * 32 + (lane & 7)) * 36 +
         ((lane >> 3) & 1) * 4 + (lane >> 4) * 8) * 4;

    int p = 0;
    for (int c = 0; c < NC; ++c) {
        cp_wait1();
        __syncthreads();

        const uint32_t base = sb + p * STAGEB;
#pragma unroll
        for (int q = 0; q < 2; ++q) {          // kc pair (2q, 2q+1)
            uint32_t bb[4][4];
#pragma unroll
            for (int nt = 0; nt < 4; ++nt)
                ldsm4(bb[nt], base + lmB + nt * (8 * 144) + q * 64);
#pragma unroll
            for (int kh = 0; kh < 2; ++kh) {   // kc = 2q + kh
                uint32_t a[4][4];
#pragma unroll
                for (int mt = 0; mt < 4; ++mt)
                    ldsm4(a[mt], base + lmA + mt * (16 * 144) + (2 * q + kh) * 32);
#pragma unroll
                for (int mt = 0; mt < 4; ++mt)
#pragma unroll
                    for (int nt = 0; nt < 4; ++nt)
                        mma_tf32(acc[mt][nt], a[mt], &bb[nt][kh * 2]);
            }
        }
        if (c + 2 < NC) {
            int pn = p + 2; if (pn >= 3) pn -= 3;
            stage(c + 2, pn);
        }
        cp_commit();
        p = (p == 2) ? 0 : p + 1;
    }
    __syncthreads();

    // ---- epilogue: spill relu(acc+b) rounded, then coalesced store ----
    float* S = smf;   // [128][132], aliases stages 0-1
#pragma unroll
    for (int mt = 0; mt < 4; ++mt) {
        const int row0 = warpM * 64 + mt * 16 + (lane >> 2);
#pragma unroll
        for (int nt = 0; nt < 4; ++nt) {
            const int sc = warpN * 32 + nt * 8 + (lane & 3) * 2;
            *(float2*)&S[row0 * 132 + sc] =
                make_float2(tf32r(fmaxf(acc[mt][nt][0] + bs[nt].x, 0.f)),
                            tf32r(fmaxf(acc[mt][nt][1] + bs[nt].y, 0.f)));
            *(float2*)&S[(row0 + 8) * 132 + sc] =
                make_float2(tf32r(fmaxf(acc[mt][nt][2] + bs[nt].x, 0.f)),
                            tf32r(fmaxf(acc[mt][nt][3] + bs[nt].y, 0.f)));
        }
    }
    __syncthreads();

    for (int e = tid; e < 128 * 32; e += 256) {
        const int row = e >> 5, cq = e & 31;
        if (row >= MROWS || batch0 + row / GN >= CB) continue;
        const float4 v = *(const float4*)&S[row * 132 + cq * 4];
        *(float4*)&hdst[(size_t)(batch0 * GN + row) * 512 + n0 + cq * 4] = v;
    }
}

// ---------------------------------------------------------------------------
// Layer 2: out = relu(NA @ (h @ W2) + b2) * nw ; STORE ? '=' : '+='.
// Grid: x = n-tile (fast, 2), y = batch-block, z = group offset.
// ---------------------------------------------------------------------------
template<int GN, int BB, int GNP, int NIB, bool STORE>
__global__ __launch_bounds__(256, 2)
void gcn_l2(const float* __restrict__ b2,
            const float* __restrict__ fw,
            float* __restrict__ dout, int gbase)
{
    constexpr int K     = 512;
    constexpr int KC    = 32;
    constexpr int NC    = K / KC;      // 16
    constexpr int MROWS = BB * GN;

    extern __shared__ char smem[];
    float* smf = (float*)smem;
    const uint32_t sb = smem_u32(smem);

    const int tid  = threadIdx.x;
    const int lane = tid & 31;
    const int wid  = tid >> 5;
    const int warpM = wid >> 2;
    const int warpN = wid & 3;
    const int G      = gbase + blockIdx.z;
    const int n0     = blockIdx.x * 128;
    const int batch0 = blockIdx.y * BB;

    const float* Asrc = g_h + hpre(G) * (size_t)CB * 512;
    const float* Bsrc = g_W2r + (size_t)G * 256 * 512;   // [n][k]
    const float* bias = b2 + G * 256;

    float nw;
    {
        float w[5];
#pragma unroll
        for (int q = 0; q < 5; ++q) w[q] = fw[q];
        float m = w[0];
#pragma unroll
        for (int q = 1; q < 5; ++q) m = fmaxf(m, w[q]);
        float s = 0.f, e[5];
#pragma unroll
        for (int q = 0; q < 5; ++q) { e[q] = expf(w[q] - m); s += e[q]; }
        nw = e[G] / s;
    }

    const float* aSrc[4]; uint32_t aDst[4];
    const float* bSrc[4]; uint32_t bDst[4];
#pragma unroll
    for (int i = 0; i < 4; ++i) {
        const int idx = i * 256 + tid;
        const int row = idx >> 3, kq = idx & 7;
        const bool valid = (row < MROWS) && (batch0 + row / GN < CB);
        aSrc[i] = (valid ? Asrc + (size_t)(batch0 * GN + row) * 512 : Asrc) + kq * 4;
        aDst[i] = row * 144 + kq * 16;
        bSrc[i] = Bsrc + (size_t)(n0 + row) * K + kq * 4;
        bDst[i] = SA_B + row * 144 + kq * 16;
    }
    auto stage = [&](int c, int p) {
        const uint32_t base = sb + p * STAGEB;
#pragma unroll
        for (int i = 0; i < 4; ++i) cp16(base + aDst[i], aSrc[i] + c * KC);
#pragma unroll
        for (int i = 0; i < 4; ++i) cp16(base + bDst[i], bSrc[i] + c * KC);
    };

    float acc[4][4][4];
#pragma unroll
    for (int mt = 0; mt < 4; ++mt)
#pragma unroll
        for (int nt = 0; nt < 4; ++nt)
#pragma unroll
            for (int r = 0; r < 4; ++r) acc[mt][nt][r] = 0.f;

    stage(0, 0); cp_commit();
    stage(1, 1); cp_commit();

    const uint32_t lmA =
        ((warpM * 64 + (lane & 7) + ((lane >> 3) & 1) * 8) * 36 +
         (lane >> 4) * 4) * 4;
    const uint32_t lmB = SA_B +
        ((warpN * 32 + (lane & 7)) * 36 +
         ((lane >> 3) & 1) * 4 + (lane >> 4) * 8) * 4;

    int p = 0;
    for (int c = 0; c < NC; ++c) {
        cp_wait1();
        __syncthreads();

        const uint32_t base = sb + p * STAGEB;
#pragma unroll
        for (int q = 0; q < 2; ++q) {
            uint32_t bb[4][4];
#pragma unroll
            for (int nt = 0; nt < 4; ++nt)
                ldsm4(bb[nt], base + lmB + nt * (8 * 144) + q * 64);
#pragma unroll
            for (int kh = 0; kh < 2; ++kh) {
                uint32_t a[4][4];
#pragma unroll
                for (int mt = 0; mt < 4; ++mt)
                    ldsm4(a[mt], base + lmA + mt * (16 * 144) + (2 * q + kh) * 32);
#pragma unroll
                for (int mt = 0; mt < 4; ++mt)
#pragma unroll
                    for (int nt = 0; nt < 4; ++nt)
                        mma_tf32(acc[mt][nt], a[mt], &bb[nt][kh * 2]);
            }
        }
        if (c + 2 < NC) {
            int pn = p + 2; if (pn >= 3) pn -= 3;
            stage(c + 2, pn);
        }
        cp_commit();
        p = (p == 2) ? 0 : p + 1;
    }
    __syncthreads();

    // ---- epilogue: spill raw acc + load NAt (overlapped), then aggregate ----
    float* S = smf;                         // [128][132]
    float* NAt_s = (float*)(smem + NAT_SOFF);
#pragma unroll
    for (int mt = 0; mt < 4; ++mt) {
        const int row0 = warpM * 64 + mt * 16 + (lane >> 2);
#pragma unroll
        for (int nt = 0; nt < 4; ++nt) {
            const int sc = warpN * 32 + nt * 8 + (lane & 3) * 2;
            *(float2*)&S[row0 * 132 + sc] = make_float2(acc[mt][nt][0], acc[mt][nt][1]);
            *(float2*)&S[(row0 + 8) * 132 + sc] = make_float2(acc[mt][nt][2], acc[mt][nt][3]);
        }
    }
    for (int e = tid; e < BB * GN * GNP; e += 256) {
        const int bb = e / (GN * GNP);
        const int r  = e - bb * (GN * GNP);
        NAt_s[e] = (batch0 + bb < CB)
                 ? g_nat[(size_t)(batch0 + bb) * 1096 + natoff(G) + r] : 0.f;
    }
    __syncthreads();

    constexpr int NU = BB * NIB * 32;
    for (int u = tid; u < NU; u += 256) {
        const int cg = u & 31;
        const int t  = u >> 5;
        const int b  = t / NIB;
        const int i0 = (t - b * NIB) * 8;
        const int batch = batch0 + b;
        if (batch >= CB) continue;
        const int icnt = (GN - i0 < 8) ? (GN - i0) : 8;

        uint64_t o[8][2];
#pragma unroll
        for (int ii = 0; ii < 8; ++ii) { o[ii][0] = 0; o[ii][1] = 0; }
        const float* Srow = S + (b * GN) * 132 + cg * 4;
        const float* natb = NAt_s + b * (GN * GNP) + i0;
#pragma unroll
        for (int j = 0; j < GN; ++j) {
            const ulonglong2 s2 = *(const ulonglong2*)(Srow + (size_t)j * 132);
            const float4 nA = *(const float4*)(natb + j * GNP);
            const float4 nB = *(const float4*)(natb + j * GNP + 4);
            const float na[8] = {nA.x, nA.y, nA.z, nA.w, nB.x, nB.y, nB.z, nB.w};
#pragma unroll
            for (int ii = 0; ii < 8; ++ii) {
                const uint64_t d = packf2(na[ii]);
                fmaf2(o[ii][0], d, s2.x);
                fmaf2(o[ii][1], d, s2.y);
            }
        }
        const int col = n0 + cg * 4;
        const float4 bv = *(const float4*)&bias[col];
#pragma unroll
        for (int ii = 0; ii < 8; ++ii) {
            if (ii >= icnt) break;
            float4 v = make_float4(
                fmaxf(__uint_as_float((uint32_t)o[ii][0]) + bv.x, 0.f) * nw,
                fmaxf(__uint_as_float((uint32_t)(o[ii][0] >> 32)) + bv.y, 0.f) * nw,
                fmaxf(__uint_as_float((uint32_t)o[ii][1]) + bv.z, 0.f) * nw,
                fmaxf(__uint_as_float((uint32_t)(o[ii][1] >> 32)) + bv.w, 0.f) * nw);
            float* dst = dout + ((size_t)batch * NNODES + GIDX[G][i0 + ii]) * 256 + col;
            if (STORE) {
                *(float4*)dst = v;
            } else {
                float4 q = *(const float4*)dst;
                q.x += v.x; q.y += v.y; q.z += v.z; q.w += v.w;
                *(float4*)dst = q;
            }
        }
    }
}

extern "C" void kernel_launch(void* const* d_in, const int* in_sizes, int n_in,
                              void* d_out, int out_size) {
    (void)in_sizes; (void)n_in; (void)out_size;
    const float* x   = (const float*)d_in[0];
    const float* adj = (const float*)d_in[1];
    const float* W1  = (const float*)d_in[2];
    const float* b1  = (const float*)d_in[3];
    const float* W2  = (const float*)d_in[4];
    const float* b2  = (const float*)d_in[5];
    const float* fw  = (const float*)d_in[6];
    float* out = (float*)d_out;

    wround<<<2560, 256>>>(W1, W2);
    aggx<<<CB, 256>>>(x, adj);

#define RUN1(GBASE, NZ, GN, BB)                                                 \
    do {                                                                        \
        auto kfn = gcn_l1<GN, BB>;                                              \
        cudaFuncSetAttribute(kfn, cudaFuncAttributeMaxDynamicSharedMemorySize,  \
                             STAGE3);                                           \
        dim3 grid(4, (CB + BB - 1) / BB, NZ);                                   \
        kfn<<<grid, 256, STAGE3>>>(b1, GBASE);                                  \
    } while (0)
#define RUN2(GBASE, NZ, GN, BB, GNP, NIB, STORE)                                \
    do {                                                                        \
        auto kfn = gcn_l2<GN, BB, GNP, NIB, STORE>;                             \
        cudaFuncSetAttribute(kfn, cudaFuncAttributeMaxDynamicSharedMemorySize,  \
                             STAGE3);                                           \
        dim3 grid(2, (CB + BB - 1) / BB, NZ);                                   \
        kfn<<<grid, 256, STAGE3>>>(b2, fw, out, GBASE);                         \
    } while (0)

    RUN1(0, 1, 25,  5);
    RUN1(1, 1,  9, 14);
    RUN1(2, 1,  7, 18);
    RUN1(3, 2,  6, 21);   // g3 + g4 merged via blockIdx.z

    RUN2(0, 1, 25,  5, 32, 4, true);    // '='
    RUN2(1, 1,  9, 14, 16, 2, false);   // '+=' (stream-ordered, deterministic)
    RUN2(2, 1,  7, 18,  8, 1, false);
    RUN2(3, 2,  6, 21,  8, 1, false);   // g3 + g4 merged
#undef RUN1
#undef RUN2
}

// round 15
// speedup vs baseline: 1.5094x; 1.5094x over previous
#include <cuda_runtime.h>
#include <cstdint>
#include <cmath>

#define CB 8192
#define NNODES 25
// group sizes: 25, 9, 7, 6, 6

__constant__ int GIDX[5][25] = {
  {0,1,2,3,4,5,6,7,8,9,10,11,12,13,14,15,16,17,18,19,20,21,22,23,24},
  {0,1,2,3,4,5,6,7,8, 0,0,0,0,0,0,0,0,0,0,0,0,0,0,0,0},
  {0,9,10,11,12,13,14, 0,0,0,0,0,0,0,0,0,0,0,0,0,0,0,0,0,0},
  {6,7,8,12,13,14, 0,0,0,0,0,0,0,0,0,0,0,0,0,0,0,0,0,0,0},
  {3,4,5,9,10,11, 0,0,0,0,0,0,0,0,0,0,0,0,0,0,0,0,0,0,0}
};

// device scratch (no allocations allowed) — all LOGICAL k-order (R13 layout)
__device__ float g_h  [(size_t)CB * 53 * 512];  // h = relu(xa@W1+b1), tf32-rounded
__device__ float g_xa [(size_t)CB * 53 * 256];  // xa = NA@x (tf32-rounded)
__device__ float g_nat[(size_t)CB * 1096];      // NA, padded, j-major per group
__device__ float g_W1r[5 * 256 * 512];          // tf32-rounded W1 [g][k][n]
__device__ float g_W2r[5 * 512 * 256];          // tf32-rounded W2 [g][k][n]

__host__ __device__ constexpr size_t hpre(int g) {
    return g == 0 ? 0 : g == 1 ? 25 : g == 2 ? 34 : g == 3 ? 41 : 47;
}
__host__ __device__ constexpr int natoff(int g) {
    return g == 0 ? 0 : g == 1 ? 800 : g == 2 ? 944 : g == 3 ? 1000 : 1048;
}

__device__ __forceinline__ uint32_t smem_u32(const void* p) {
    uint32_t a;
    asm("{ .reg .u64 t; cvta.to.shared.u64 t, %1; cvt.u32.u64 %0, t; }"
        : "=r"(a) : "l"(p));
    return a;
}
__device__ __forceinline__ float tf32r(float v) {
    uint32_t o;
    asm("cvt.rna.tf32.f32 %0, %1;" : "=r"(o) : "f"(v));
    return __uint_as_float(o);
}
__device__ __forceinline__ void cp16(uint32_t dst, const void* src) {
    asm volatile("cp.async.cg.shared.global [%0], [%1], 16;"
                 :: "r"(dst), "l"(src) : "memory");
}
__device__ __forceinline__ void cp_commit() {
    asm volatile("cp.async.commit_group;" ::: "memory");
}
__device__ __forceinline__ void cp_wait1() {
    asm volatile("cp.async.wait_group 1;" ::: "memory");
}
__device__ __forceinline__ void ldsm4(uint32_t* r, uint32_t addr) {
    asm volatile("ldmatrix.sync.aligned.m8n8.x4.shared.b16 {%0,%1,%2,%3}, [%4];"
        : "=r"(r[0]), "=r"(r[1]), "=r"(r[2]), "=r"(r[3]) : "r"(addr));
}
__device__ __forceinline__ void mma_tf32(float* d, const uint32_t* a, const uint32_t* b) {
    asm volatile(
        "mma.sync.aligned.m16n8k8.row.col.f32.tf32.tf32.f32 "
        "{%0,%1,%2,%3}, {%4,%5,%6,%7}, {%8,%9}, {%0,%1,%2,%3};"
        : "+f"(d[0]), "+f"(d[1]), "+f"(d[2]), "+f"(d[3])
        : "r"(a[0]), "r"(a[1]), "r"(a[2]), "r"(a[3]), "r"(b[0]), "r"(b[1]));
}
__device__ __forceinline__ uint64_t packf2(float v) {
    uint64_t d;
    asm("mov.b64 %0, {%1, %1};" : "=l"(d) : "r"(__float_as_uint(v)));
    return d;
}
__device__ __forceinline__ void fmaf2(uint64_t& o, uint64_t a, uint64_t b) {
    asm("fma.rn.f32x2 %0, %1, %2, %0;" : "+l"(o) : "l"(a), "l"(b));
}

// ---------------------------------------------------------------------------
// Weight rounding pre-pass (coalesced, layout [g][k][n])
// ---------------------------------------------------------------------------
__global__ void wround(const float* __restrict__ W1, const float* __restrict__ W2) {
    const int t = blockIdx.x * 256 + threadIdx.x;
    constexpr int WN4 = 5 * 256 * 512 / 4;
    if (t < WN4) {
        float4 v = ((const float4*)W1)[t];
        v.x = tf32r(v.x); v.y = tf32r(v.y); v.z = tf32r(v.z); v.w = tf32r(v.w);
        ((float4*)g_W1r)[t] = v;
        v = ((const float4*)W2)[t];
        v.x = tf32r(v.x); v.y = tf32r(v.y); v.z = tf32r(v.z); v.w = tf32r(v.w);
        ((float4*)g_W2r)[t] = v;
    }
}

// ---------------------------------------------------------------------------
// Pre-pass: per batch, NA per group (padded j-major) and xa = NA @ x.
// ---------------------------------------------------------------------------
template<int G, int GN, int GNP>
__device__ void aggx_group(int b, int tid, const float* xs, const float* adjs,
                           float* na_s, float* dinv) {
    if (tid < GN) {
        float deg = 1.f;
#pragma unroll
        for (int j = 0; j < GN; ++j)
            deg += adjs[GIDX[G][tid] * 25 + GIDX[G][j]];
        dinv[tid] = rsqrtf(deg);
    }
    __syncthreads();
    for (int e = tid; e < GN * GN; e += 256) {
        const int i = e / GN, j = e - i * GN;
        float v = adjs[GIDX[G][i] * 25 + GIDX[G][j]] + (i == j ? 1.f : 0.f);
        na_s[e] = v * dinv[i] * dinv[j];
    }
    __syncthreads();
    float* natd = g_nat + (size_t)b * 1096 + natoff(G);
    for (int e = tid; e < GN * GNP; e += 256) {
        const int j = e / GNP, i = e - j * GNP;
        natd[e] = (i < GN) ? na_s[i * GN + j] : 0.f;
    }
    float* xad = g_xa + hpre(G) * (size_t)CB * 256 + (size_t)b * GN * 256;
    for (int u = tid; u < GN * 64; u += 256) {
        const int i = u >> 6, c = (u & 63) * 4;
        float4 o = make_float4(0.f, 0.f, 0.f, 0.f);
#pragma unroll
        for (int j = 0; j < GN; ++j) {
            const float na = na_s[i * GN + j];
            const float4 xv = *(const float4*)&xs[GIDX[G][j] * 260 + c];
            o.x += na * xv.x; o.y += na * xv.y;
            o.z += na * xv.z; o.w += na * xv.w;
        }
        o.x = tf32r(o.x); o.y = tf32r(o.y); o.z = tf32r(o.z); o.w = tf32r(o.w);
        *(float4*)&xad[i * 256 + c] = o;
    }
    __syncthreads();
}

__global__ __launch_bounds__(256)
void aggx(const float* __restrict__ x, const float* __restrict__ adj) {
    __shared__ float xs[25 * 260];
    __shared__ float adjs[625];
    __shared__ float na_s[625];
    __shared__ float dinv[25];
    const int b = blockIdx.x, tid = threadIdx.x;
    for (int e = tid; e < 25 * 256; e += 256) {
        const int row = e >> 8, col = e & 255;
        xs[row * 260 + col] = x[(size_t)b * 6400 + e];
    }
    for (int e = tid; e < 625; e += 256) adjs[e] = adj[(size_t)b * 625 + e];
    __syncthreads();
    aggx_group<0, 25, 32>(b, tid, xs, adjs, na_s, dinv);
    aggx_group<1,  9, 16>(b, tid, xs, adjs, na_s, dinv);
    aggx_group<2,  7,  8>(b, tid, xs, adjs, na_s, dinv);
    aggx_group<3,  6,  8>(b, tid, xs, adjs, na_s, dinv);
    aggx_group<4,  6,  8>(b, tid, xs, adjs, na_s, dinv);
}

// KC=32 chunk, 3-stage ring (CUTLASS discipline). A stride 36f: 8 ldmatrix
// row-addresses hit byte offsets {0,16,...,112} mod 128 -> conflict-free LDSM.
#define SA_B   (128 * 36 * 4)      // 18432
#define SB_B   (32 * 136 * 4)      // 17408
#define STAGEB (SA_B + SB_B)       // 35840
#define STAGE3 (3 * STAGEB)        // 107520
#define NAT_SOFF 68608             // NAt epilogue home, above S[128][132]

// one kc step of the warp-tile MMA (A via ldmatrix, B via scalar LDS)
#define KC_STEP(kc)                                                             \
    do {                                                                        \
        uint32_t a[4][4], b[4][2];                                              \
        _Pragma("unroll")                                                       \
        for (int mt = 0; mt < 4; ++mt)                                          \
            ldsm4(a[mt], base + lmA + mt * (16 * 144) + (kc) * 32);             \
        _Pragma("unroll")                                                       \
        for (int nt = 0; nt < 4; ++nt)                                          \
            _Pragma("unroll")                                                   \
            for (int r = 0; r < 2; ++r)                                         \
                b[nt][r] = sBp[(bRow + (kc) * 8 + r * 4) * 136 + bCol + nt * 8];\
        _Pragma("unroll")                                                       \
        for (int mt = 0; mt < 4; ++mt)                                          \
            _Pragma("unroll")                                                   \
            for (int nt = 0; nt < 4; ++nt)                                      \
                mma_tf32(acc[mt][nt], a[mt], b[nt]);                            \
    } while (0)

// ---------------------------------------------------------------------------
// Layer 1: h = relu(xa @ W1 + b1) -> g_h (tf32-rounded). Pure GEMM.
// Grid: x = n-tile (fast), y = batch-block, z = group offset.
// ---------------------------------------------------------------------------
template<int GN, int BB>
__global__ __launch_bounds__(256, 2)
void gcn_l1(const float* __restrict__ b1, int gbase)
{
    constexpr int K     = 256;
    constexpr int NW    = 512;
    constexpr int KC    = 32;
    constexpr int NC    = K / KC;      // 8
    constexpr int MROWS = BB * GN;

    extern __shared__ char smem[];
    float* smf = (float*)smem;
    const uint32_t sb = smem_u32(smem);

    const int tid  = threadIdx.x;
    const int lane = tid & 31;
    const int wid  = tid >> 5;
    const int warpM = wid >> 2;
    const int warpN = wid & 3;
    const int G      = gbase + blockIdx.z;
    const int n0     = blockIdx.x * 128;
    const int batch0 = blockIdx.y * BB;

    const float* Asrc = g_xa + hpre(G) * (size_t)CB * 256;
    const float* Bsrc = g_W1r + (size_t)G * 256 * 512;
    const float* bias = b1 + G * 512;
    float* hdst = g_h + hpre(G) * (size_t)CB * 512;

    const float* aSrc[4]; uint32_t aDst[4];
    const float* bSrc[4]; uint32_t bDst[4];
#pragma unroll
    for (int i = 0; i < 4; ++i) {
        const int idx = i * 256 + tid;        // 0..1023
        const int row = idx >> 3, kq = idx & 7;
        const bool valid = (row < MROWS) && (batch0 + row / GN < CB);
        aSrc[i] = (valid ? Asrc + (size_t)(batch0 * GN + row) * 256 : Asrc) + kq * 4;
        aDst[i] = row * 144 + kq * 16;
        const int kk = idx >> 5, nq = idx & 31;
        bSrc[i] = Bsrc + (size_t)kk * NW + n0 + nq * 4;
        bDst[i] = SA_B + kk * 544 + nq * 16;
    }
    auto stage = [&](int c, int p) {
        const uint32_t base2 = sb + p * STAGEB;
#pragma unroll
        for (int i = 0; i < 4; ++i) cp16(base2 + aDst[i], aSrc[i] + c * KC);
#pragma unroll
        for (int i = 0; i < 4; ++i) cp16(base2 + bDst[i], bSrc[i] + (size_t)c * KC * NW);
    };

    float acc[4][4][4];
#pragma unroll
    for (int mt = 0; mt < 4; ++mt)
#pragma unroll
        for (int nt = 0; nt < 4; ++nt)
#pragma unroll
            for (int r = 0; r < 4; ++r) acc[mt][nt][r] = 0.f;

    stage(0, 0); cp_commit();
    stage(1, 1); cp_commit();

    float2 bs[4];
#pragma unroll
    for (int nt = 0; nt < 4; ++nt)
        bs[nt] = *(const float2*)&bias[n0 + warpN * 32 + nt * 8 + (lane & 3) * 2];

    const uint32_t lmA =
        ((warpM * 64 + (lane & 7) + ((lane >> 3) & 1) * 8) * 36 +
         (lane >> 4) * 4) * 4;
    const int bRow = lane & 3;
    const int bCol = warpN * 32 + (lane >> 2);

    int p = 0;
    for (int c = 0; c < NC; ++c) {
        cp_wait1();
        __syncthreads();

        const uint32_t base = sb + p * STAGEB;
        const uint32_t* sBp = (const uint32_t*)(smem + p * STAGEB + SA_B);

        KC_STEP(0);
        KC_STEP(1);
        // mid-chunk staging: copies get a half-chunk head start under MMAs
        if (c + 2 < NC) {
            int pn = p + 2; if (pn >= 3) pn -= 3;
            stage(c + 2, pn);
        }
        cp_commit();
        KC_STEP(2);
        KC_STEP(3);

        p = (p == 2) ? 0 : p + 1;
    }
    __syncthreads();

    // ---- epilogue: spill relu(acc+b) rounded, then coalesced store ----
    float* S = smf;   // [128][132], aliases stages 0-1
#pragma unroll
    for (int mt = 0; mt < 4; ++mt) {
        const int row0 = warpM * 64 + mt * 16 + (lane >> 2);
#pragma unroll
        for (int nt = 0; nt < 4; ++nt) {
            const int sc = warpN * 32 + nt * 8 + (lane & 3) * 2;
            *(float2*)&S[row0 * 132 + sc] =
                make_float2(tf32r(fmaxf(acc[mt][nt][0] + bs[nt].x, 0.f)),
                            tf32r(fmaxf(acc[mt][nt][1] + bs[nt].y, 0.f)));
            *(float2*)&S[(row0 + 8) * 132 + sc] =
                make_float2(tf32r(fmaxf(acc[mt][nt][2] + bs[nt].x, 0.f)),
                            tf32r(fmaxf(acc[mt][nt][3] + bs[nt].y, 0.f)));
        }
    }
    __syncthreads();

    for (int e = tid; e < 128 * 32; e += 256) {
        const int row = e >> 5, cq = e & 31;
        if (row >= MROWS || batch0 + row / GN >= CB) continue;
        const float4 v = *(const float4*)&S[row * 132 + cq * 4];
        *(float4*)&hdst[(size_t)(batch0 * GN + row) * 512 + n0 + cq * 4] = v;
    }
}

// ---------------------------------------------------------------------------
// Layer 2: out = relu(NA @ (h @ W2) + b2) * nw ; STORE ? '=' : '+='.
// Grid: x = n-tile (fast, 2), y = batch-block, z = group offset.
// ---------------------------------------------------------------------------
template<int GN, int BB, int GNP, int NIB, bool STORE>
__global__ __launch_bounds__(256, 2)
void gcn_l2(const float* __restrict__ b2,
            const float* __restrict__ fw,
            float* __restrict__ dout, int gbase)
{
    constexpr int K     = 512;
    constexpr int NW    = 256;
    constexpr int KC    = 32;
    constexpr int NC    = K / KC;      // 16
    constexpr int MROWS = BB * GN;

    extern __shared__ char smem[];
    float* smf = (float*)smem;
    const uint32_t sb = smem_u32(smem);

    const int tid  = threadIdx.x;
    const int lane = tid & 31;
    const int wid  = tid >> 5;
    const int warpM = wid >> 2;
    const int warpN = wid & 3;
    const int G      = gbase + blockIdx.z;
    const int n0     = blockIdx.x * 128;
    const int batch0 = blockIdx.y * BB;

    const float* Asrc = g_h + hpre(G) * (size_t)CB * 512;
    const float* Bsrc = g_W2r + (size_t)G * 512 * 256;
    const float* bias = b2 + G * 256;

    float nw;
    {
        float w[5];
#pragma unroll
        for (int q = 0; q < 5; ++q) w[q] = fw[q];
        float m = w[0];
#pragma unroll
        for (int q = 1; q < 5; ++q) m = fmaxf(m, w[q]);
        float s = 0.f, e[5];
#pragma unroll
        for (int q = 0; q < 5; ++q) { e[q] = expf(w[q] - m); s += e[q]; }
        nw = e[G] / s;
    }

    const float* aSrc[4]; uint32_t aDst[4];
    const float* bSrc[4]; uint32_t bDst[4];
#pragma unroll
    for (int i = 0; i < 4; ++i) {
        const int idx = i * 256 + tid;
        const int row = idx >> 3, kq = idx & 7;
        const bool valid = (row < MROWS) && (batch0 + row / GN < CB);
        aSrc[i] = (valid ? Asrc + (size_t)(batch0 * GN + row) * 512 : Asrc) + kq * 4;
        aDst[i] = row * 144 + kq * 16;
        const int kk = idx >> 5, nq = idx & 31;
        bSrc[i] = Bsrc + (size_t)kk * NW + n0 + nq * 4;
        bDst[i] = SA_B + kk * 544 + nq * 16;
    }
    auto stage = [&](int c, int p) {
        const uint32_t base2 = sb + p * STAGEB;
#pragma unroll
        for (int i = 0; i < 4; ++i) cp16(base2 + aDst[i], aSrc[i] + c * KC);
#pragma unroll
        for (int i = 0; i < 4; ++i) cp16(base2 + bDst[i], bSrc[i] + (size_t)c * KC * NW);
    };

    float acc[4][4][4];
#pragma unroll
    for (int mt = 0; mt < 4; ++mt)
#pragma unroll
        for (int nt = 0; nt < 4; ++nt)
#pragma unroll
            for (int r = 0; r < 4; ++r) acc[mt][nt][r] = 0.f;

    stage(0, 0); cp_commit();
    stage(1, 1); cp_commit();

    const uint32_t lmA =
        ((warpM * 64 + (lane & 7) + ((lane >> 3) & 1) * 8) * 36 +
         (lane >> 4) * 4) * 4;
    const int bRow = lane & 3;
    const int bCol = warpN * 32 + (lane >> 2);

    int p = 0;
    for (int c = 0; c < NC; ++c) {
        cp_wait1();
        __syncthreads();

        const uint32_t base = sb + p * STAGEB;
        const uint32_t* sBp = (const uint32_t*)(smem + p * STAGEB + SA_B);

        KC_STEP(0);
        KC_STEP(1);
        if (c + 2 < NC) {
            int pn = p + 2; if (pn >= 3) pn -= 3;
            stage(c + 2, pn);
        }
        cp_commit();
        KC_STEP(2);
        KC_STEP(3);

        p = (p == 2) ? 0 : p + 1;
    }
    __syncthreads();

    // ---- epilogue: spill raw acc + load NAt (overlapped), then aggregate ----
    float* S = smf;                         // [128][132]
    float* NAt_s = (float*)(smem + NAT_SOFF);
#pragma unroll
    for (int mt = 0; mt < 4; ++mt) {
        const int row0 = warpM * 64 + mt * 16 + (lane >> 2);
#pragma unroll
        for (int nt = 0; nt < 4; ++nt) {
            const int sc = warpN * 32 + nt * 8 + (lane & 3) * 2;
            *(float2*)&S[row0 * 132 + sc] = make_float2(acc[mt][nt][0], acc[mt][nt][1]);
            *(float2*)&S[(row0 + 8) * 132 + sc] = make_float2(acc[mt][nt][2], acc[mt][nt][3]);
        }
    }
    for (int e = tid; e < BB * GN * GNP; e += 256) {
        const int bb = e / (GN * GNP);
        const int r  = e - bb * (GN * GNP);
        NAt_s[e] = (batch0 + bb < CB)
                 ? g_nat[(size_t)(batch0 + bb) * 1096 + natoff(G) + r] : 0.f;
    }
    __syncthreads();

    constexpr int NU = BB * NIB * 32;
    for (int u = tid; u < NU; u += 256) {
        const int cg = u & 31;
        const int t  = u >> 5;
        const int b  = t / NIB;
        const int i0 = (t - b * NIB) * 8;
        const int batch = batch0 + b;
        if (batch >= CB) continue;
        const int icnt = (GN - i0 < 8) ? (GN - i0) : 8;

        uint64_t o[8][2];
#pragma unroll
        for (int ii = 0; ii < 8; ++ii) { o[ii][0] = 0; o[ii][1] = 0; }
        const float* Srow = S + (b * GN) * 132 + cg * 4;
        const float* natb = NAt_s + b * (GN * GNP) + i0;
#pragma unroll
        for (int j = 0; j < GN; ++j) {
            const ulonglong2 s2 = *(const ulonglong2*)(Srow + (size_t)j * 132);
            const float4 nA = *(const float4*)(natb + j * GNP);
            const float4 nB = *(const float4*)(natb + j * GNP + 4);
            const float na[8] = {nA.x, nA.y, nA.z, nA.w, nB.x, nB.y, nB.z, nB.w};
#pragma unroll
            for (int ii = 0; ii < 8; ++ii) {
                const uint64_t d = packf2(na[ii]);
                fmaf2(o[ii][0], d, s2.x);
                fmaf2(o[ii][1], d, s2.y);
            }
        }
        const int col = n0 + cg * 4;
        const float4 bv = *(const float4*)&bias[col];
#pragma unroll
        for (int ii = 0; ii < 8; ++ii) {
            if (ii >= icnt) break;
            float4 v = make_float4(
                fmaxf(__uint_as_float((uint32_t)o[ii][0]) + bv.x, 0.f) * nw,
                fmaxf(__uint_as_float((uint32_t)(o[ii][0] >> 32)) + bv.y, 0.f) * nw,
                fmaxf(__uint_as_float((uint32_t)o[ii][1]) + bv.z, 0.f) * nw,
                fmaxf(__uint_as_float((uint32_t)(o[ii][1] >> 32)) + bv.w, 0.f) * nw);
            float* dst = dout + ((size_t)batch * NNODES + GIDX[G][i0 + ii]) * 256 + col;
            if (STORE) {
                *(float4*)dst = v;
            } else {
                float4 q = *(const float4*)dst;
                q.x += v.x; q.y += v.y; q.z += v.z; q.w += v.w;
                *(float4*)dst = q;
            }
        }
    }
}

extern "C" void kernel_launch(void* const* d_in, const int* in_sizes, int n_in,
                              void* d_out, int out_size) {
    (void)in_sizes; (void)n_in; (void)out_size;
    const float* x   = (const float*)d_in[0];
    const float* adj = (const float*)d_in[1];
    const float* W1  = (const float*)d_in[2];
    const float* b1  = (const float*)d_in[3];
    const float* W2  = (const float*)d_in[4];
    const float* b2  = (const float*)d_in[5];
    const float* fw  = (const float*)d_in[6];
    float* out = (float*)d_out;

    wround<<<640, 256>>>(W1, W2);
    aggx<<<CB, 256>>>(x, adj);

#define RUN1(GBASE, NZ, GN, BB)                                                 \
    do {                                                                        \
        auto kfn = gcn_l1<GN, BB>;                                              \
        cudaFuncSetAttribute(kfn, cudaFuncAttributeMaxDynamicSharedMemorySize,  \
                             STAGE3);                                           \
        dim3 grid(4, (CB + BB - 1) / BB, NZ);                                   \
        kfn<<<grid, 256, STAGE3>>>(b1, GBASE);                                  \
    } while (0)
#define RUN2(GBASE, NZ, GN, BB, GNP, NIB, STORE)                                \
    do {                                                                        \
        auto kfn = gcn_l2<GN, BB, GNP, NIB, STORE>;                             \
        cudaFuncSetAttribute(kfn, cudaFuncAttributeMaxDynamicSharedMemorySize,  \
                             STAGE3);                                           \
        dim3 grid(2, (CB + BB - 1) / BB, NZ);                                   \
        kfn<<<grid, 256, STAGE3>>>(b2, fw, out, GBASE);                         \
    } while (0)

    RUN1(0, 1, 25,  5);
    RUN1(1, 1,  9, 14);
    RUN1(2, 1,  7, 18);
    RUN1(3, 2,  6, 21);   // g3 + g4 merged via blockIdx.z

    RUN2(0, 1, 25,  5, 32, 4, true);    // '='
    RUN2(1, 1,  9, 14, 16, 2, false);   // '+=' (stream-ordered, deterministic)
    RUN2(2, 1,  7, 18,  8, 1, false);
    RUN2(3, 2,  6, 21,  8, 1, false);   // g3 + g4 merged
#undef RUN1
#undef RUN2
}

// round 16
// speedup vs baseline: 1.5655x; 1.0372x over previous
#include <cuda_runtime.h>
#include <cstdint>
#include <cmath>

#define CB 8192
#define NNODES 25
// group sizes: 25, 9, 7, 6, 6

__constant__ int GIDX[5][25] = {
  {0,1,2,3,4,5,6,7,8,9,10,11,12,13,14,15,16,17,18,19,20,21,22,23,24},
  {0,1,2,3,4,5,6,7,8, 0,0,0,0,0,0,0,0,0,0,0,0,0,0,0,0},
  {0,9,10,11,12,13,14, 0,0,0,0,0,0,0,0,0,0,0,0,0,0,0,0,0,0},
  {6,7,8,12,13,14, 0,0,0,0,0,0,0,0,0,0,0,0,0,0,0,0,0,0,0},
  {3,4,5,9,10,11, 0,0,0,0,0,0,0,0,0,0,0,0,0,0,0,0,0,0,0}
};

// device scratch (no allocations allowed) — all LOGICAL k-order (R13 layout)
__device__ float g_h  [(size_t)CB * 53 * 512];  // h = relu(xa@W1+b1), tf32-rounded
__device__ float g_xa [(size_t)CB * 53 * 256];  // xa = NA@x (tf32-rounded)
__device__ float g_nat[(size_t)CB * 1096];      // NA, padded, j-major per group
__device__ float g_W1r[5 * 256 * 512];          // tf32-rounded W1 [g][k][n]
__device__ float g_W2r[5 * 512 * 256];          // tf32-rounded W2 [g][k][n]

__host__ __device__ constexpr size_t hpre(int g) {
    return g == 0 ? 0 : g == 1 ? 25 : g == 2 ? 34 : g == 3 ? 41 : 47;
}
__host__ __device__ constexpr int natoff(int g) {
    return g == 0 ? 0 : g == 1 ? 800 : g == 2 ? 944 : g == 3 ? 1000 : 1048;
}

__device__ __forceinline__ uint32_t smem_u32(const void* p) {
    uint32_t a;
    asm("{ .reg .u64 t; cvta.to.shared.u64 t, %1; cvt.u32.u64 %0, t; }"
        : "=r"(a) : "l"(p));
    return a;
}
__device__ __forceinline__ float tf32r(float v) {
    uint32_t o;
    asm("cvt.rna.tf32.f32 %0, %1;" : "=r"(o) : "f"(v));
    return __uint_as_float(o);
}
__device__ __forceinline__ void cp16(uint32_t dst, const void* src) {
    asm volatile("cp.async.cg.shared.global [%0], [%1], 16;"
                 :: "r"(dst), "l"(src) : "memory");
}
__device__ __forceinline__ void cp_commit() {
    asm volatile("cp.async.commit_group;" ::: "memory");
}
__device__ __forceinline__ void cp_wait1() {
    asm volatile("cp.async.wait_group 1;" ::: "memory");
}
__device__ __forceinline__ void ldsm4(uint32_t* r, uint32_t addr) {
    asm volatile("ldmatrix.sync.aligned.m8n8.x4.shared.b16 {%0,%1,%2,%3}, [%4];"
        : "=r"(r[0]), "=r"(r[1]), "=r"(r[2]), "=r"(r[3]) : "r"(addr));
}
__device__ __forceinline__ void mma_tf32(float* d, const uint32_t* a, const uint32_t* b) {
    asm volatile(
        "mma.sync.aligned.m16n8k8.row.col.f32.tf32.tf32.f32 "
        "{%0,%1,%2,%3}, {%4,%5,%6,%7}, {%8,%9}, {%0,%1,%2,%3};"
        : "+f"(d[0]), "+f"(d[1]), "+f"(d[2]), "+f"(d[3])
        : "r"(a[0]), "r"(a[1]), "r"(a[2]), "r"(a[3]), "r"(b[0]), "r"(b[1]));
}
__device__ __forceinline__ uint64_t packf2(float v) {
    uint64_t d;
    asm("mov.b64 %0, {%1, %1};" : "=l"(d) : "r"(__float_as_uint(v)));
    return d;
}
__device__ __forceinline__ void fmaf2(uint64_t& o, uint64_t a, uint64_t b) {
    asm("fma.rn.f32x2 %0, %1, %2, %0;" : "+l"(o) : "l"(a), "l"(b));
}

// ---------------------------------------------------------------------------
// Weight rounding pre-pass (coalesced, layout [g][k][n])
// ---------------------------------------------------------------------------
__global__ void wround(const float* __restrict__ W1, const float* __restrict__ W2) {
    const int t = blockIdx.x * 256 + threadIdx.x;
    constexpr int WN4 = 5 * 256 * 512 / 4;
    if (t < WN4) {
        float4 v = ((const float4*)W1)[t];
        v.x = tf32r(v.x); v.y = tf32r(v.y); v.z = tf32r(v.z); v.w = tf32r(v.w);
        ((float4*)g_W1r)[t] = v;
        v = ((const float4*)W2)[t];
        v.x = tf32r(v.x); v.y = tf32r(v.y); v.z = tf32r(v.z); v.w = tf32r(v.w);
        ((float4*)g_W2r)[t] = v;
    }
}

// ---------------------------------------------------------------------------
// Pre-pass: one (batch, group) per CTA. NA (padded j-major) + xa = NA @ x.
// Same summation order as before -> bit-identical results.
// ---------------------------------------------------------------------------
template<int G, int GN, int GNP>
__device__ void aggx_dev(int b, int tid, const float* __restrict__ x,
                         const float* __restrict__ adj,
                         float* na_s, float* dinv) {
    const float* adjb = adj + (size_t)b * 625;
    if (tid < GN) {
        float deg = 1.f;
#pragma unroll
        for (int j = 0; j < GN; ++j)
            deg += adjb[GIDX[G][tid] * 25 + GIDX[G][j]];
        dinv[tid] = rsqrtf(deg);
    }
    __syncthreads();
    for (int e = tid; e < GN * GN; e += 256) {
        const int i = e / GN, j = e - i * GN;
        float v = adjb[GIDX[G][i] * 25 + GIDX[G][j]] + (i == j ? 1.f : 0.f);
        na_s[e] = v * dinv[i] * dinv[j];
    }
    __syncthreads();
    float* natd = g_nat + (size_t)b * 1096 + natoff(G);
    for (int e = tid; e < GN * GNP; e += 256) {
        const int j = e / GNP, i = e - j * GNP;
        natd[e] = (i < GN) ? na_s[i * GN + j] : 0.f;
    }
    const float* xb = x + (size_t)b * 6400;
    float* xad = g_xa + hpre(G) * (size_t)CB * 256 + (size_t)b * GN * 256;
    for (int u = tid; u < GN * 64; u += 256) {
        const int i = u >> 6, c = (u & 63) * 4;
        float4 o = make_float4(0.f, 0.f, 0.f, 0.f);
#pragma unroll
        for (int j = 0; j < GN; ++j) {
            const float na = na_s[i * GN + j];
            const float4 xv = *(const float4*)&xb[GIDX[G][j] * 256 + c];
            o.x += na * xv.x; o.y += na * xv.y;
            o.z += na * xv.z; o.w += na * xv.w;
        }
        o.x = tf32r(o.x); o.y = tf32r(o.y); o.z = tf32r(o.z); o.w = tf32r(o.w);
        *(float4*)&xad[i * 256 + c] = o;
    }
}

__global__ __launch_bounds__(256)
void aggx(const float* __restrict__ x, const float* __restrict__ adj) {
    __shared__ float na_s[625];
    __shared__ float dinv[25];
    const int b = blockIdx.x, tid = threadIdx.x;
    switch (blockIdx.y) {
        case 0:  aggx_dev<0, 25, 32>(b, tid, x, adj, na_s, dinv); break;
        case 1:  aggx_dev<1,  9, 16>(b, tid, x, adj, na_s, dinv); break;
        case 2:  aggx_dev<2,  7,  8>(b, tid, x, adj, na_s, dinv); break;
        case 3:  aggx_dev<3,  6,  8>(b, tid, x, adj, na_s, dinv); break;
        default: aggx_dev<4,  6,  8>(b, tid, x, adj, na_s, dinv); break;
    }
}

// KC=32 chunk, 3-stage ring (CUTLASS discipline). A stride 36f: 8 ldmatrix
// row-addresses hit byte offsets {0,16,...,112} mod 128 -> conflict-free LDSM.
#define SA_B   (128 * 36 * 4)      // 18432
#define SB_B   (32 * 136 * 4)      // 17408
#define STAGEB (SA_B + SB_B)       // 35840
#define STAGE3 (3 * STAGEB)        // 107520
#define NAT_SOFF 68608             // NAt epilogue home, above S[128][132]

// ---------------------------------------------------------------------------
// Layer 1: h = relu(xa @ W1 + b1) -> g_h (tf32-rounded). Pure GEMM.
// Grid: x = n-tile (fast), y = batch-block, z = group offset.
// ---------------------------------------------------------------------------
template<int GN, int BB>
__global__ __launch_bounds__(256, 2)
void gcn_l1(const float* __restrict__ b1, int gbase)
{
    constexpr int K     = 256;
    constexpr int NW    = 512;
    constexpr int KC    = 32;
    constexpr int NC    = K / KC;      // 8
    constexpr int MROWS = BB * GN;

    extern __shared__ char smem[];
    float* smf = (float*)smem;
    const uint32_t sb = smem_u32(smem);

    const int tid  = threadIdx.x;
    const int lane = tid & 31;
    const int wid  = tid >> 5;
    const int warpM = wid >> 2;
    const int warpN = wid & 3;
    const int G      = gbase + blockIdx.z;
    const int n0     = blockIdx.x * 128;
    const int batch0 = blockIdx.y * BB;

    const float* Asrc = g_xa + hpre(G) * (size_t)CB * 256;
    const float* Bsrc = g_W1r + (size_t)G * 256 * 512;
    const float* bias = b1 + G * 512;
    float* hdst = g_h + hpre(G) * (size_t)CB * 512;

    const float* aSrc[4]; uint32_t aDst[4];
    const float* bSrc[4]; uint32_t bDst[4];
#pragma unroll
    for (int i = 0; i < 4; ++i) {
        const int idx = i * 256 + tid;        // 0..1023
        const int row = idx >> 3, kq = idx & 7;
        const bool valid = (row < MROWS) && (batch0 + row / GN < CB);
        aSrc[i] = (valid ? Asrc + (size_t)(batch0 * GN + row) * 256 : Asrc) + kq * 4;
        aDst[i] = row * 144 + kq * 16;
        const int kk = idx >> 5, nq = idx & 31;
        bSrc[i] = Bsrc + (size_t)kk * NW + n0 + nq * 4;
        bDst[i] = SA_B + kk * 544 + nq * 16;
    }
    auto stage = [&](int c, int p) {
        const uint32_t base = sb + p * STAGEB;
#pragma unroll
        for (int i = 0; i < 4; ++i) cp16(base + aDst[i], aSrc[i] + c * KC);
#pragma unroll
        for (int i = 0; i < 4; ++i) cp16(base + bDst[i], bSrc[i] + (size_t)c * KC * NW);
    };

    float acc[4][4][4];
#pragma unroll
    for (int mt = 0; mt < 4; ++mt)
#pragma unroll
        for (int nt = 0; nt < 4; ++nt)
#pragma unroll
            for (int r = 0; r < 4; ++r) acc[mt][nt][r] = 0.f;

    stage(0, 0); cp_commit();
    stage(1, 1); cp_commit();

    float2 bs[4];
#pragma unroll
    for (int nt = 0; nt < 4; ++nt)
        bs[nt] = *(const float2*)&bias[n0 + warpN * 32 + nt * 8 + (lane & 3) * 2];

    const uint32_t lmA =
        ((warpM * 64 + (lane & 7) + ((lane >> 3) & 1) * 8) * 36 +
         (lane >> 4) * 4) * 4;
    const int bRow = lane & 3;
    const int bCol = warpN * 32 + (lane >> 2);

    int p = 0;
    for (int c = 0; c < NC; ++c) {
        cp_wait1();
        __syncthreads();

        const uint32_t base = sb + p * STAGEB;
        const uint32_t* sBp = (const uint32_t*)(smem + p * STAGEB + SA_B);
#pragma unroll
        for (int kc = 0; kc < 4; ++kc) {
            uint32_t a[4][4], b[4][2];
#pragma unroll
            for (int mt = 0; mt < 4; ++mt)
                ldsm4(a[mt], base + lmA + mt * (16 * 144) + kc * 32);
#pragma unroll
            for (int nt = 0; nt < 4; ++nt)
#pragma unroll
                for (int r = 0; r < 2; ++r)
                    b[nt][r] = sBp[(bRow + kc * 8 + r * 4) * 136 + bCol + nt * 8];
#pragma unroll
            for (int mt = 0; mt < 4; ++mt)
#pragma unroll
                for (int nt = 0; nt < 4; ++nt)
                    mma_tf32(acc[mt][nt], a[mt], b[nt]);
        }
        if (c + 2 < NC) {
            int pn = p + 2; if (pn >= 3) pn -= 3;
            stage(c + 2, pn);
        }
        cp_commit();
        p = (p == 2) ? 0 : p + 1;
    }
    __syncthreads();

    // ---- epilogue: spill relu(acc+b) rounded, then coalesced store ----
    float* S = smf;   // [128][132], aliases stages 0-1
#pragma unroll
    for (int mt = 0; mt < 4; ++mt) {
        const int row0 = warpM * 64 + mt * 16 + (lane >> 2);
#pragma unroll
        for (int nt = 0; nt < 4; ++nt) {
            const int sc = warpN * 32 + nt * 8 + (lane & 3) * 2;
            *(float2*)&S[row0 * 132 + sc] =
                make_float2(tf32r(fmaxf(acc[mt][nt][0] + bs[nt].x, 0.f)),
                            tf32r(fmaxf(acc[mt][nt][1] + bs[nt].y, 0.f)));
            *(float2*)&S[(row0 + 8) * 132 + sc] =
                make_float2(tf32r(fmaxf(acc[mt][nt][2] + bs[nt].x, 0.f)),
                            tf32r(fmaxf(acc[mt][nt][3] + bs[nt].y, 0.f)));
        }
    }
    __syncthreads();

    for (int e = tid; e < 128 * 32; e += 256) {
        const int row = e >> 5, cq = e & 31;
        if (row >= MROWS || batch0 + row / GN >= CB) continue;
        const float4 v = *(const float4*)&S[row * 132 + cq * 4];
        *(float4*)&hdst[(size_t)(batch0 * GN + row) * 512 + n0 + cq * 4] = v;
    }
}

// ---------------------------------------------------------------------------
// Layer 2: out = relu(NA @ (h @ W2) + b2) * nw ; STORE ? '=' : '+='.
// Grid: x = n-tile (fast, 2), y = batch-block, z = group offset.
// ---------------------------------------------------------------------------
template<int GN, int BB, int GNP, int NIB, bool STORE>
__global__ __launch_bounds__(256, 2)
void gcn_l2(const float* __restrict__ b2,
            const float* __restrict__ fw,
            float* __restrict__ dout, int gbase)
{
    constexpr int K     = 512;
    constexpr int NW    = 256;
    constexpr int KC    = 32;
    constexpr int NC    = K / KC;      // 16
    constexpr int MROWS = BB * GN;

    extern __shared__ char smem[];
    float* smf = (float*)smem;
    const uint32_t sb = smem_u32(smem);

    const int tid  = threadIdx.x;
    const int lane = tid & 31;
    const int wid  = tid >> 5;
    const int warpM = wid >> 2;
    const int warpN = wid & 3;
    const int G      = gbase + blockIdx.z;
    const int n0     = blockIdx.x * 128;
    const int batch0 = blockIdx.y * BB;

    const float* Asrc = g_h + hpre(G) * (size_t)CB * 512;
    const float* Bsrc = g_W2r + (size_t)G * 512 * 256;
    const float* bias = b2 + G * 256;

    float nw;
    {
        float w[5];
#pragma unroll
        for (int q = 0; q < 5; ++q) w[q] = fw[q];
        float m = w[0];
#pragma unroll
        for (int q = 1; q < 5; ++q) m = fmaxf(m, w[q]);
        float s = 0.f, e[5];
#pragma unroll
        for (int q = 0; q < 5; ++q) { e[q] = expf(w[q] - m); s += e[q]; }
        nw = e[G] / s;
    }

    const float* aSrc[4]; uint32_t aDst[4];
    const float* bSrc[4]; uint32_t bDst[4];
#pragma unroll
    for (int i = 0; i < 4; ++i) {
        const int idx = i * 256 + tid;
        const int row = idx >> 3, kq = idx & 7;
        const bool valid = (row < MROWS) && (batch0 + row / GN < CB);
        aSrc[i] = (valid ? Asrc + (size_t)(batch0 * GN + row) * 512 : Asrc) + kq * 4;
        aDst[i] = row * 144 + kq * 16;
        const int kk = idx >> 5, nq = idx & 31;
        bSrc[i] = Bsrc + (size_t)kk * NW + n0 + nq * 4;
        bDst[i] = SA_B + kk * 544 + nq * 16;
    }
    auto stage = [&](int c, int p) {
        const uint32_t base = sb + p * STAGEB;
#pragma unroll
        for (int i = 0; i < 4; ++i) cp16(base + aDst[i], aSrc[i] + c * KC);
#pragma unroll
        for (int i = 0; i < 4; ++i) cp16(base + bDst[i], bSrc[i] + (size_t)c * KC * NW);
    };

    float acc[4][4][4];
#pragma unroll
    for (int mt = 0; mt < 4; ++mt)
#pragma unroll
        for (int nt = 0; nt < 4; ++nt)
#pragma unroll
            for (int r = 0; r < 4; ++r) acc[mt][nt][r] = 0.f;

    stage(0, 0); cp_commit();
    stage(1, 1); cp_commit();

    const uint32_t lmA =
        ((warpM * 64 + (lane & 7) + ((lane >> 3) & 1) * 8) * 36 +
         (lane >> 4) * 4) * 4;
    const int bRow = lane & 3;
    const int bCol = warpN * 32 + (lane >> 2);

    int p = 0;
    for (int c = 0; c < NC; ++c) {
        cp_wait1();
        __syncthreads();

        const uint32_t base = sb + p * STAGEB;
        const uint32_t* sBp = (const uint32_t*)(smem + p * STAGEB + SA_B);
#pragma unroll
        for (int kc = 0; kc < 4; ++kc) {
            uint32_t a[4][4], b[4][2];
#pragma unroll
            for (int mt = 0; mt < 4; ++mt)
                ldsm4(a[mt], base + lmA + mt * (16 * 144) + kc * 32);
#pragma unroll
            for (int nt = 0; nt < 4; ++nt)
#pragma unroll
                for (int r = 0; r < 2; ++r)
                    b[nt][r] = sBp[(bRow + kc * 8 + r * 4) * 136 + bCol + nt * 8];
#pragma unroll
            for (int mt = 0; mt < 4; ++mt)
#pragma unroll
                for (int nt = 0; nt < 4; ++nt)
                    mma_tf32(acc[mt][nt], a[mt], b[nt]);
        }
        if (c + 2 < NC) {
            int pn = p + 2; if (pn >= 3) pn -= 3;
            stage(c + 2, pn);
        }
        cp_commit();
        p = (p == 2) ? 0 : p + 1;
    }
    __syncthreads();

    // ---- epilogue: spill raw acc + load NAt (overlapped), then aggregate ----
    float* S = smf;                         // [128][132]
    float* NAt_s = (float*)(smem + NAT_SOFF);
#pragma unroll
    for (int mt = 0; mt < 4; ++mt) {
        const int row0 = warpM * 64 + mt * 16 + (lane >> 2);
#pragma unroll
        for (int nt = 0; nt < 4; ++nt) {
            const int sc = warpN * 32 + nt * 8 + (lane & 3) * 2;
            *(float2*)&S[row0 * 132 + sc] = make_float2(acc[mt][nt][0], acc[mt][nt][1]);
            *(float2*)&S[(row0 + 8) * 132 + sc] = make_float2(acc[mt][nt][2], acc[mt][nt][3]);
        }
    }
    for (int e = tid; e < BB * GN * GNP; e += 256) {
        const int bb = e / (GN * GNP);
        const int r  = e - bb * (GN * GNP);
        NAt_s[e] = (batch0 + bb < CB)
                 ? g_nat[(size_t)(batch0 + bb) * 1096 + natoff(G) + r] : 0.f;
    }
    __syncthreads();

    constexpr int NU = BB * NIB * 32;
    for (int u = tid; u < NU; u += 256) {
        const int cg = u & 31;
        const int t  = u >> 5;
        const int b  = t / NIB;
        const int i0 = (t - b * NIB) * 8;
        const int batch = batch0 + b;
        if (batch >= CB) continue;
        const int icnt = (GN - i0 < 8) ? (GN - i0) : 8;

        uint64_t o[8][2];
#pragma unroll
        for (int ii = 0; ii < 8; ++ii) { o[ii][0] = 0; o[ii][1] = 0; }
        const float* Srow = S + (b * GN) * 132 + cg * 4;
        const float* natb = NAt_s + b * (GN * GNP) + i0;
#pragma unroll
        for (int j = 0; j < GN; ++j) {
            const ulonglong2 s2 = *(const ulonglong2*)(Srow + (size_t)j * 132);
            const float4 nA = *(const float4*)(natb + j * GNP);
            const float4 nB = *(const float4*)(natb + j * GNP + 4);
            const float na[8] = {nA.x, nA.y, nA.z, nA.w, nB.x, nB.y, nB.z, nB.w};
#pragma unroll
            for (int ii = 0; ii < 8; ++ii) {
                const uint64_t d = packf2(na[ii]);
                fmaf2(o[ii][0], d, s2.x);
                fmaf2(o[ii][1], d, s2.y);
            }
        }
        const int col = n0 + cg * 4;
        const float4 bv = *(const float4*)&bias[col];
#pragma unroll
        for (int ii = 0; ii < 8; ++ii) {
            if (ii >= icnt) break;
            float4 v = make_float4(
                fmaxf(__uint_as_float((uint32_t)o[ii][0]) + bv.x, 0.f) * nw,
                fmaxf(__uint_as_float((uint32_t)(o[ii][0] >> 32)) + bv.y, 0.f) * nw,
                fmaxf(__uint_as_float((uint32_t)o[ii][1]) + bv.z, 0.f) * nw,
                fmaxf(__uint_as_float((uint32_t)(o[ii][1] >> 32)) + bv.w, 0.f) * nw);
            float* dst = dout + ((size_t)batch * NNODES + GIDX[G][i0 + ii]) * 256 + col;
            if (STORE) {
                *(float4*)dst = v;
            } else {
                float4 q = *(const float4*)dst;
                q.x += v.x; q.y += v.y; q.z += v.z; q.w += v.w;
                *(float4*)dst = q;
            }
        }
    }
}

extern "C" void kernel_launch(void* const* d_in, const int* in_sizes, int n_in,
                              void* d_out, int out_size) {
    (void)in_sizes; (void)n_in; (void)out_size;
    const float* x   = (const float*)d_in[0];
    const float* adj = (const float*)d_in[1];
    const float* W1  = (const float*)d_in[2];
    const float* b1  = (const float*)d_in[3];
    const float* W2  = (const float*)d_in[4];
    const float* b2  = (const float*)d_in[5];
    const float* fw  = (const float*)d_in[6];
    float* out = (float*)d_out;

    wround<<<640, 256>>>(W1, W2);
    aggx<<<dim3(CB, 5), 256>>>(x, adj);

#define RUN1(GBASE, NZ, GN, BB)                                                 \
    do {                                                                        \
        auto kfn = gcn_l1<GN, BB>;                                              \
        cudaFuncSetAttribute(kfn, cudaFuncAttributeMaxDynamicSharedMemorySize,  \
                             STAGE3);                                           \
        dim3 grid(4, (CB + BB - 1) / BB, NZ);                                   \
        kfn<<<grid, 256, STAGE3>>>(b1, GBASE);                                  \
    } while (0)
#define RUN2(GBASE, NZ, GN, BB, GNP, NIB, STORE)                                \
    do {                                                                        \
        auto kfn = gcn_l2<GN, BB, GNP, NIB, STORE>;                             \
        cudaFuncSetAttribute(kfn, cudaFuncAttributeMaxDynamicSharedMemorySize,  \
                             STAGE3);                                           \
        dim3 grid(2, (CB + BB - 1) / BB, NZ);                                   \
        kfn<<<grid, 256, STAGE3>>>(b2, fw, out, GBASE);                         \
    } while (0)

    RUN1(0, 1, 25,  5);
    RUN1(1, 1,  9, 14);
    RUN1(2, 1,  7, 18);
    RUN1(3, 2,  6, 21);   // g3 + g4 merged via blockIdx.z

    RUN2(0, 1, 25,  5, 32, 4, true);    // '='
    RUN2(1, 1,  9, 14, 16, 2, false);   // '+=' (stream-ordered, deterministic)
    RUN2(2, 1,  7, 18,  8, 1, false);
    RUN2(3, 2,  6, 21,  8, 1, false);   // g3 + g4 merged
#undef RUN1
#undef RUN2
}

// round 17
// speedup vs baseline: 1.5831x; 1.0112x over previous
#include <cuda_runtime.h>
#include <cstdint>
#include <cmath>

#define CB 8192
#define NNODES 25
// group sizes: 25, 9, 7, 6, 6

__constant__ int GIDX[5][25] = {
  {0,1,2,3,4,5,6,7,8,9,10,11,12,13,14,15,16,17,18,19,20,21,22,23,24},
  {0,1,2,3,4,5,6,7,8, 0,0,0,0,0,0,0,0,0,0,0,0,0,0,0,0},
  {0,9,10,11,12,13,14, 0,0,0,0,0,0,0,0,0,0,0,0,0,0,0,0,0,0},
  {6,7,8,12,13,14, 0,0,0,0,0,0,0,0,0,0,0,0,0,0,0,0,0,0,0},
  {3,4,5,9,10,11, 0,0,0,0,0,0,0,0,0,0,0,0,0,0,0,0,0,0,0}
};

// device scratch (no allocations allowed) — all LOGICAL k-order (R13 layout)
__device__ float g_h  [(size_t)CB * 53 * 512];  // h = relu(xa@W1+b1), tf32-rounded
__device__ float g_xa [(size_t)CB * 53 * 256];  // xa = NA@x (tf32-rounded)
__device__ float g_nat[(size_t)CB * 1096];      // NA, padded, j-major per group
__device__ float g_W1r[5 * 256 * 512];          // tf32-rounded W1 [g][k][n]
__device__ float g_W2r[5 * 512 * 256];          // tf32-rounded W2 [g][k][n]

__host__ __device__ constexpr size_t hpre(int g) {
    return g == 0 ? 0 : g == 1 ? 25 : g == 2 ? 34 : g == 3 ? 41 : 47;
}
__host__ __device__ constexpr int natoff(int g) {
    return g == 0 ? 0 : g == 1 ? 800 : g == 2 ? 944 : g == 3 ? 1000 : 1048;
}

__device__ __forceinline__ uint32_t smem_u32(const void* p) {
    uint32_t a;
    asm("{ .reg .u64 t; cvta.to.shared.u64 t, %1; cvt.u32.u64 %0, t; }"
        : "=r"(a) : "l"(p));
    return a;
}
__device__ __forceinline__ float tf32r(float v) {
    uint32_t o;
    asm("cvt.rna.tf32.f32 %0, %1;" : "=r"(o) : "f"(v));
    return __uint_as_float(o);
}
__device__ __forceinline__ void cp16(uint32_t dst, const void* src) {
    asm volatile("cp.async.cg.shared.global [%0], [%1], 16;"
                 :: "r"(dst), "l"(src) : "memory");
}
__device__ __forceinline__ void cp_commit() {
    asm volatile("cp.async.commit_group;" ::: "memory");
}
__device__ __forceinline__ void cp_wait1() {
    asm volatile("cp.async.wait_group 1;" ::: "memory");
}
__device__ __forceinline__ void ldsm4(uint32_t* r, uint32_t addr) {
    asm volatile("ldmatrix.sync.aligned.m8n8.x4.shared.b16 {%0,%1,%2,%3}, [%4];"
        : "=r"(r[0]), "=r"(r[1]), "=r"(r[2]), "=r"(r[3]) : "r"(addr));
}
__device__ __forceinline__ void mma_tf32(float* d, const uint32_t* a, const uint32_t* b) {
    asm volatile(
        "mma.sync.aligned.m16n8k8.row.col.f32.tf32.tf32.f32 "
        "{%0,%1,%2,%3}, {%4,%5,%6,%7}, {%8,%9}, {%0,%1,%2,%3};"
        : "+f"(d[0]), "+f"(d[1]), "+f"(d[2]), "+f"(d[3])
        : "r"(a[0]), "r"(a[1]), "r"(a[2]), "r"(a[3]), "r"(b[0]), "r"(b[1]));
}
__device__ __forceinline__ uint64_t packf2(float v) {
    uint64_t d;
    asm("mov.b64 %0, {%1, %1};" : "=l"(d) : "r"(__float_as_uint(v)));
    return d;
}
__device__ __forceinline__ void fmaf2(uint64_t& o, uint64_t a, uint64_t b) {
    asm("fma.rn.f32x2 %0, %1, %2, %0;" : "+l"(o) : "l"(a), "l"(b));
}

// ---------------------------------------------------------------------------
// Weight rounding pre-pass (coalesced, layout [g][k][n])
// ---------------------------------------------------------------------------
__global__ void wround(const float* __restrict__ W1, const float* __restrict__ W2) {
    const int t = blockIdx.x * 256 + threadIdx.x;
    constexpr int WN4 = 5 * 256 * 512 / 4;
    if (t < WN4) {
        float4 v = ((const float4*)W1)[t];
        v.x = tf32r(v.x); v.y = tf32r(v.y); v.z = tf32r(v.z); v.w = tf32r(v.w);
        ((float4*)g_W1r)[t] = v;
        v = ((const float4*)W2)[t];
        v.x = tf32r(v.x); v.y = tf32r(v.y); v.z = tf32r(v.z); v.w = tf32r(v.w);
        ((float4*)g_W2r)[t] = v;
    }
}

// ---------------------------------------------------------------------------
// Pre-pass: one (batch, group) per CTA. NA (padded j-major) + xa = NA @ x.
// ---------------------------------------------------------------------------
template<int G, int GN, int GNP>
__device__ void aggx_dev(int b, int tid, const float* __restrict__ x,
                         const float* __restrict__ adj,
                         float* na_s, float* dinv) {
    const float* adjb = adj + (size_t)b * 625;
    if (tid < GN) {
        float deg = 1.f;
#pragma unroll
        for (int j = 0; j < GN; ++j)
            deg += adjb[GIDX[G][tid] * 25 + GIDX[G][j]];
        dinv[tid] = rsqrtf(deg);
    }
    __syncthreads();
    for (int e = tid; e < GN * GN; e += 256) {
        const int i = e / GN, j = e - i * GN;
        float v = adjb[GIDX[G][i] * 25 + GIDX[G][j]] + (i == j ? 1.f : 0.f);
        na_s[e] = v * dinv[i] * dinv[j];
    }
    __syncthreads();
    float* natd = g_nat + (size_t)b * 1096 + natoff(G);
    for (int e = tid; e < GN * GNP; e += 256) {
        const int j = e / GNP, i = e - j * GNP;
        natd[e] = (i < GN) ? na_s[i * GN + j] : 0.f;
    }
    const float* xb = x + (size_t)b * 6400;
    float* xad = g_xa + hpre(G) * (size_t)CB * 256 + (size_t)b * GN * 256;
    for (int u = tid; u < GN * 64; u += 256) {
        const int i = u >> 6, c = (u & 63) * 4;
        float4 o = make_float4(0.f, 0.f, 0.f, 0.f);
#pragma unroll
        for (int j = 0; j < GN; ++j) {
            const float na = na_s[i * GN + j];
            const float4 xv = *(const float4*)&xb[GIDX[G][j] * 256 + c];
            o.x += na * xv.x; o.y += na * xv.y;
            o.z += na * xv.z; o.w += na * xv.w;
        }
        o.x = tf32r(o.x); o.y = tf32r(o.y); o.z = tf32r(o.z); o.w = tf32r(o.w);
        *(float4*)&xad[i * 256 + c] = o;
    }
}

__global__ __launch_bounds__(256)
void aggx(const float* __restrict__ x, const float* __restrict__ adj) {
    __shared__ float na_s[625];
    __shared__ float dinv[25];
    const int b = blockIdx.x, tid = threadIdx.x;
    switch (blockIdx.y) {
        case 0:  aggx_dev<0, 25, 32>(b, tid, x, adj, na_s, dinv); break;
        case 1:  aggx_dev<1,  9, 16>(b, tid, x, adj, na_s, dinv); break;
        case 2:  aggx_dev<2,  7,  8>(b, tid, x, adj, na_s, dinv); break;
        case 3:  aggx_dev<3,  6,  8>(b, tid, x, adj, na_s, dinv); break;
        default: aggx_dev<4,  6,  8>(b, tid, x, adj, na_s, dinv); break;
    }
}

// KC=32 chunk, 3-stage ring (CUTLASS discipline). A stride 36f: conflict-free LDSM.
#define SA_B   (128 * 36 * 4)      // 18432
#define SB_B   (32 * 136 * 4)      // 17408
#define STAGEB (SA_B + SB_B)       // 35840
#define STAGE3 (3 * STAGEB)        // 107520
#define NAT_SOFF 68608             // NAt epilogue home, above S[128][132]

// ---------------------------------------------------------------------------
// Layer 1: h = relu(xa @ W1 + b1) -> g_h (tf32-rounded). Pure GEMM.
// ---------------------------------------------------------------------------
template<int GN, int BB>
__global__ __launch_bounds__(256, 2)
void gcn_l1(const float* __restrict__ b1, int gbase)
{
    constexpr int K     = 256;
    constexpr int NW    = 512;
    constexpr int KC    = 32;
    constexpr int NC    = K / KC;
    constexpr int MROWS = BB * GN;

    extern __shared__ char smem[];
    float* smf = (float*)smem;
    const uint32_t sb = smem_u32(smem);

    const int tid  = threadIdx.x;
    const int lane = tid & 31;
    const int wid  = tid >> 5;
    const int warpM = wid >> 2;
    const int warpN = wid & 3;
    const int G      = gbase + blockIdx.z;
    const int n0     = blockIdx.x * 128;
    const int batch0 = blockIdx.y * BB;

    const float* Asrc = g_xa + hpre(G) * (size_t)CB * 256;
    const float* Bsrc = g_W1r + (size_t)G * 256 * 512;
    const float* bias = b1 + G * 512;
    float* hdst = g_h + hpre(G) * (size_t)CB * 512;

    const float* aSrc[4]; uint32_t aDst[4];
    const float* bSrc[4]; uint32_t bDst[4];
#pragma unroll
    for (int i = 0; i < 4; ++i) {
        const int idx = i * 256 + tid;
        const int row = idx >> 3, kq = idx & 7;
        const bool valid = (row < MROWS) && (batch0 + row / GN < CB);
        aSrc[i] = (valid ? Asrc + (size_t)(batch0 * GN + row) * 256 : Asrc) + kq * 4;
        aDst[i] = row * 144 + kq * 16;
        const int kk = idx >> 5, nq = idx & 31;
        bSrc[i] = Bsrc + (size_t)kk * NW + n0 + nq * 4;
        bDst[i] = SA_B + kk * 544 + nq * 16;
    }
    auto stage = [&](int c, int p) {
        const uint32_t base = sb + p * STAGEB;
#pragma unroll
        for (int i = 0; i < 4; ++i) cp16(base + aDst[i], aSrc[i] + c * KC);
#pragma unroll
        for (int i = 0; i < 4; ++i) cp16(base + bDst[i], bSrc[i] + (size_t)c * KC * NW);
    };

    float acc[4][4][4];
#pragma unroll
    for (int mt = 0; mt < 4; ++mt)
#pragma unroll
        for (int nt = 0; nt < 4; ++nt)
#pragma unroll
            for (int r = 0; r < 4; ++r) acc[mt][nt][r] = 0.f;

    stage(0, 0); cp_commit();
    stage(1, 1); cp_commit();

    float2 bs[4];
#pragma unroll
    for (int nt = 0; nt < 4; ++nt)
        bs[nt] = *(const float2*)&bias[n0 + warpN * 32 + nt * 8 + (lane & 3) * 2];

    const uint32_t lmA =
        ((warpM * 64 + (lane & 7) + ((lane >> 3) & 1) * 8) * 36 +
         (lane >> 4) * 4) * 4;
    const int bRow = lane & 3;
    const int bCol = warpN * 32 + (lane >> 2);

    int p = 0;
    for (int c = 0; c < NC; ++c) {
        cp_wait1();
        __syncthreads();

        const uint32_t base = sb + p * STAGEB;
        const uint32_t* sBp = (const uint32_t*)(smem + p * STAGEB + SA_B);
#pragma unroll
        for (int kc = 0; kc < 4; ++kc) {
            uint32_t a[4][4], b[4][2];
#pragma unroll
            for (int mt = 0; mt < 4; ++mt)
                ldsm4(a[mt], base + lmA + mt * (16 * 144) + kc * 32);
#pragma unroll
            for (int nt = 0; nt < 4; ++nt)
#pragma unroll
                for (int r = 0; r < 2; ++r)
                    b[nt][r] = sBp[(bRow + kc * 8 + r * 4) * 136 + bCol + nt * 8];
#pragma unroll
            for (int mt = 0; mt < 4; ++mt)
#pragma unroll
                for (int nt = 0; nt < 4; ++nt)
                    mma_tf32(acc[mt][nt], a[mt], b[nt]);
        }
        if (c + 2 < NC) {
            int pn = p + 2; if (pn >= 3) pn -= 3;
            stage(c + 2, pn);
        }
        cp_commit();
        p = (p == 2) ? 0 : p + 1;
    }
    __syncthreads();

    float* S = smf;   // [128][132]
#pragma unroll
    for (int mt = 0; mt < 4; ++mt) {
        const int row0 = warpM * 64 + mt * 16 + (lane >> 2);
#pragma unroll
        for (int nt = 0; nt < 4; ++nt) {
            const int sc = warpN * 32 + nt * 8 + (lane & 3) * 2;
            *(float2*)&S[row0 * 132 + sc] =
                make_float2(tf32r(fmaxf(acc[mt][nt][0] + bs[nt].x, 0.f)),
                            tf32r(fmaxf(acc[mt][nt][1] + bs[nt].y, 0.f)));
            *(float2*)&S[(row0 + 8) * 132 + sc] =
                make_float2(tf32r(fmaxf(acc[mt][nt][2] + bs[nt].x, 0.f)),
                            tf32r(fmaxf(acc[mt][nt][3] + bs[nt].y, 0.f)));
        }
    }
    __syncthreads();

    for (int e = tid; e < 128 * 32; e += 256) {
        const int row = e >> 5, cq = e & 31;
        if (row >= MROWS || batch0 + row / GN >= CB) continue;
        const float4 v = *(const float4*)&S[row * 132 + cq * 4];
        *(float4*)&hdst[(size_t)(batch0 * GN + row) * 512 + n0 + cq * 4] = v;
    }
}

// ---------------------------------------------------------------------------
// Layer 2: out = relu(NA @ (h @ W2) + b2) * nw ; STORE ? '=' : '+='.
// ---------------------------------------------------------------------------
template<int GN, int BB, int GNP, int NIB, bool STORE>
__global__ __launch_bounds__(256, 2)
void gcn_l2(const float* __restrict__ b2,
            const float* __restrict__ fw,
            float* __restrict__ dout, int gbase)
{
    constexpr int K     = 512;
    constexpr int NW    = 256;
    constexpr int KC    = 32;
    constexpr int NC    = K / KC;
    constexpr int MROWS = BB * GN;

    extern __shared__ char smem[];
    float* smf = (float*)smem;
    const uint32_t sb = smem_u32(smem);

    const int tid  = threadIdx.x;
    const int lane = tid & 31;
    const int wid  = tid >> 5;
    const int warpM = wid >> 2;
    const int warpN = wid & 3;
    const int G      = gbase + blockIdx.z;
    const int n0     = blockIdx.x * 128;
    const int batch0 = blockIdx.y * BB;

    const float* Asrc = g_h + hpre(G) * (size_t)CB * 512;
    const float* Bsrc = g_W2r + (size_t)G * 512 * 256;
    const float* bias = b2 + G * 256;

    float nw;
    {
        float w[5];
#pragma unroll
        for (int q = 0; q < 5; ++q) w[q] = fw[q];
        float m = w[0];
#pragma unroll
        for (int q = 1; q < 5; ++q) m = fmaxf(m, w[q]);
        float s = 0.f, e[5];
#pragma unroll
        for (int q = 0; q < 5; ++q) { e[q] = expf(w[q] - m); s += e[q]; }
        nw = e[G] / s;
    }

    const float* aSrc[4]; uint32_t aDst[4];
    const float* bSrc[4]; uint32_t bDst[4];
#pragma unroll
    for (int i = 0; i < 4; ++i) {
        const int idx = i * 256 + tid;
        const int row = idx >> 3, kq = idx & 7;
        const bool valid = (row < MROWS) && (batch0 + row / GN < CB);
        aSrc[i] = (valid ? Asrc + (size_t)(batch0 * GN + row) * 512 : Asrc) + kq * 4;
        aDst[i] = row * 144 + kq * 16;
        const int kk = idx >> 5, nq = idx & 31;
        bSrc[i] = Bsrc + (size_t)kk * NW + n0 + nq * 4;
        bDst[i] = SA_B + kk * 544 + nq * 16;
    }
    auto stage = [&](int c, int p) {
        const uint32_t base = sb + p * STAGEB;
#pragma unroll
        for (int i = 0; i < 4; ++i) cp16(base + aDst[i], aSrc[i] + c * KC);
#pragma unroll
        for (int i = 0; i < 4; ++i) cp16(base + bDst[i], bSrc[i] + (size_t)c * KC * NW);
    };

    float acc[4][4][4];
#pragma unroll
    for (int mt = 0; mt < 4; ++mt)
#pragma unroll
        for (int nt = 0; nt < 4; ++nt)
#pragma unroll
            for (int r = 0; r < 4; ++r) acc[mt][nt][r] = 0.f;

    stage(0, 0); cp_commit();
    stage(1, 1); cp_commit();

    const uint32_t lmA =
        ((warpM * 64 + (lane & 7) + ((lane >> 3) & 1) * 8) * 36 +
         (lane >> 4) * 4) * 4;
    const int bRow = lane & 3;
    const int bCol = warpN * 32 + (lane >> 2);

    int p = 0;
    for (int c = 0; c < NC; ++c) {
        cp_wait1();
        __syncthreads();

        const uint32_t base = sb + p * STAGEB;
        const uint32_t* sBp = (const uint32_t*)(smem + p * STAGEB + SA_B);
#pragma unroll
        for (int kc = 0; kc < 4; ++kc) {
            uint32_t a[4][4], b[4][2];
#pragma unroll
            for (int mt = 0; mt < 4; ++mt)
                ldsm4(a[mt], base + lmA + mt * (16 * 144) + kc * 32);
#pragma unroll
            for (int nt = 0; nt < 4; ++nt)
#pragma unroll
                for (int r = 0; r < 2; ++r)
                    b[nt][r] = sBp[(bRow + kc * 8 + r * 4) * 136 + bCol + nt * 8];
#pragma unroll
            for (int mt = 0; mt < 4; ++mt)
#pragma unroll
                for (int nt = 0; nt < 4; ++nt)
                    mma_tf32(acc[mt][nt], a[mt], b[nt]);
        }
        if (c + 2 < NC) {
            int pn = p + 2; if (pn >= 3) pn -= 3;
            stage(c + 2, pn);
        }
        cp_commit();
        p = (p == 2) ? 0 : p + 1;
    }
    __syncthreads();

    float* S = smf;                         // [128][132]
    float* NAt_s = (float*)(smem + NAT_SOFF);
#pragma unroll
    for (int mt = 0; mt < 4; ++mt) {
        const int row0 = warpM * 64 + mt * 16 + (lane >> 2);
#pragma unroll
        for (int nt = 0; nt < 4; ++nt) {
            const int sc = warpN * 32 + nt * 8 + (lane & 3) * 2;
            *(float2*)&S[row0 * 132 + sc] = make_float2(acc[mt][nt][0], acc[mt][nt][1]);
            *(float2*)&S[(row0 + 8) * 132 + sc] = make_float2(acc[mt][nt][2], acc[mt][nt][3]);
        }
    }
    for (int e = tid; e < BB * GN * GNP; e += 256) {
        const int bb = e / (GN * GNP);
        const int r  = e - bb * (GN * GNP);
        NAt_s[e] = (batch0 + bb < CB)
                 ? g_nat[(size_t)(batch0 + bb) * 1096 + natoff(G) + r] : 0.f;
    }
    __syncthreads();

    constexpr int NU = BB * NIB * 32;
    for (int u = tid; u < NU; u += 256) {
        const int cg = u & 31;
        const int t  = u >> 5;
        const int b  = t / NIB;
        const int i0 = (t - b * NIB) * 8;
        const int batch = batch0 + b;
        if (batch >= CB) continue;
        const int icnt = (GN - i0 < 8) ? (GN - i0) : 8;

        uint64_t o[8][2];
#pragma unroll
        for (int ii = 0; ii < 8; ++ii) { o[ii][0] = 0; o[ii][1] = 0; }
        const float* Srow = S + (b * GN) * 132 + cg * 4;
        const float* natb = NAt_s + b * (GN * GNP) + i0;
#pragma unroll
        for (int j = 0; j < GN; ++j) {
            const ulonglong2 s2 = *(const ulonglong2*)(Srow + (size_t)j * 132);
            const float4 nA = *(const float4*)(natb + j * GNP);
            const float4 nB = *(const float4*)(natb + j * GNP + 4);
            const float na[8] = {nA.x, nA.y, nA.z, nA.w, nB.x, nB.y, nB.z, nB.w};
#pragma unroll
            for (int ii = 0; ii < 8; ++ii) {
                const uint64_t d = packf2(na[ii]);
                fmaf2(o[ii][0], d, s2.x);
                fmaf2(o[ii][1], d, s2.y);
            }
        }
        const int col = n0 + cg * 4;
        const float4 bv = *(const float4*)&bias[col];
#pragma unroll
        for (int ii = 0; ii < 8; ++ii) {
            if (ii >= icnt) break;
            float4 v = make_float4(
                fmaxf(__uint_as_float((uint32_t)o[ii][0]) + bv.x, 0.f) * nw,
                fmaxf(__uint_as_float((uint32_t)(o[ii][0] >> 32)) + bv.y, 0.f) * nw,
                fmaxf(__uint_as_float((uint32_t)o[ii][1]) + bv.z, 0.f) * nw,
                fmaxf(__uint_as_float((uint32_t)(o[ii][1] >> 32)) + bv.w, 0.f) * nw);
            float* dst = dout + ((size_t)batch * NNODES + GIDX[G][i0 + ii]) * 256 + col;
            if (STORE) {
                *(float4*)dst = v;
            } else {
                float4 q = *(const float4*)dst;
                q.x += v.x; q.y += v.y; q.z += v.z; q.w += v.w;
                *(float4*)dst = q;
            }
        }
    }
}

extern "C" void kernel_launch(void* const* d_in, const int* in_sizes, int n_in,
                              void* d_out, int out_size) {
    (void)in_sizes; (void)n_in; (void)out_size;
    const float* x   = (const float*)d_in[0];
    const float* adj = (const float*)d_in[1];
    const float* W1  = (const float*)d_in[2];
    const float* b1  = (const float*)d_in[3];
    const float* W2  = (const float*)d_in[4];
    const float* b2  = (const float*)d_in[5];
    const float* fw  = (const float*)d_in[6];
    float* out = (float*)d_out;

    // fork/join DAG over side streams (graph-capture legal: side streams are
    // infected via events recorded on the capture-origin stream).
    cudaStream_t s1, s2, s3;
    cudaStreamCreateWithFlags(&s1, cudaStreamNonBlocking);
    cudaStreamCreateWithFlags(&s2, cudaStreamNonBlocking);
    cudaStreamCreateWithFlags(&s3, cudaStreamNonBlocking);
    cudaEvent_t evStart, evW, evPre, e10, e20, e11, e21, e12, e22;
    cudaEventCreateWithFlags(&evStart, cudaEventDisableTiming);
    cudaEventCreateWithFlags(&evW,     cudaEventDisableTiming);
    cudaEventCreateWithFlags(&evPre,   cudaEventDisableTiming);
    cudaEventCreateWithFlags(&e10, cudaEventDisableTiming);
    cudaEventCreateWithFlags(&e20, cudaEventDisableTiming);
    cudaEventCreateWithFlags(&e11, cudaEventDisableTiming);
    cudaEventCreateWithFlags(&e21, cudaEventDisableTiming);
    cudaEventCreateWithFlags(&e12, cudaEventDisableTiming);
    cudaEventCreateWithFlags(&e22, cudaEventDisableTiming);

#define L1K(S, GBASE, NZ, GN, BB)                                               \
    do {                                                                        \
        auto kfn = gcn_l1<GN, BB>;                                              \
        cudaFuncSetAttribute(kfn, cudaFuncAttributeMaxDynamicSharedMemorySize,  \
                             STAGE3);                                           \
        dim3 grid(4, (CB + BB - 1) / BB, NZ);                                   \
        kfn<<<grid, 256, STAGE3, S>>>(b1, GBASE);                               \
    } while (0)
#define L2K(S, GBASE, NZ, GN, BB, GNP, NIB, STORE)                              \
    do {                                                                        \
        auto kfn = gcn_l2<GN, BB, GNP, NIB, STORE>;                             \
        cudaFuncSetAttribute(kfn, cudaFuncAttributeMaxDynamicSharedMemorySize,  \
                             STAGE3);                                           \
        dim3 grid(2, (CB + BB - 1) / BB, NZ);                                   \
        kfn<<<grid, 256, STAGE3, S>>>(b2, fw, out, GBASE);                      \
    } while (0)

    // origin stream (0): aggx ; s1 forked for wround in parallel
    cudaEventRecord(evStart, 0);
    cudaStreamWaitEvent(s1, evStart, 0);
    wround<<<640, 256, 0, s1>>>(W1, W2);
    cudaEventRecord(evW, s1);
    aggx<<<dim3(CB, 5), 256, 0, 0>>>(x, adj);
    cudaStreamWaitEvent(0, evW, 0);
    cudaEventRecord(evPre, 0);          // all pre-pass data ready

    // L1 kernels fan out across streams
    cudaStreamWaitEvent(s1, evPre, 0);
    L1K(s1, 0, 1, 25,  5);              // g0 (largest)
    cudaEventRecord(e10, s1);
    cudaStreamWaitEvent(s2, evPre, 0);
    L1K(s2, 1, 1,  9, 14);              // g1
    cudaEventRecord(e11, s2);
    cudaStreamWaitEvent(s3, evPre, 0);
    L1K(s3, 2, 1,  7, 18);              // g2
    cudaEventRecord(e12, s3);
    L1K((cudaStream_t)0, 3, 2, 6, 21);  // g3+g4 on origin (after evPre in-order)

    // L2 chain: g0 -> g1 -> g2 -> g34 (deterministic RMW order via events)
    cudaStreamWaitEvent(s1, e10, 0);    // no-op (in-stream) but explicit
    L2K(s1, 0, 1, 25,  5, 32, 4, true);
    cudaEventRecord(e20, s1);

    cudaStreamWaitEvent(s2, e20, 0);    // after own L1 g1 (in-stream) + L2 g0
    L2K(s2, 1, 1,  9, 14, 16, 2, false);
    cudaEventRecord(e21, s2);

    cudaStreamWaitEvent(s3, e21, 0);    // after own L1 g2 + L2 g1
    L2K(s3, 2, 1,  7, 18,  8, 1, false);
    cudaEventRecord(e22, s3);

    cudaStreamWaitEvent(0, e22, 0);     // after L1 g34 (in-stream) + L2 g2
    L2K((cudaStream_t)0, 3, 2, 6, 21,  8, 1, false);

#undef L1K
#undef L2K

    cudaEventDestroy(evStart); cudaEventDestroy(evW); cudaEventDestroy(evPre);
    cudaEventDestroy(e10); cudaEventDestroy(e20);
    cudaEventDestroy(e11); cudaEventDestroy(e21);
    cudaEventDestroy(e12); cudaEventDestroy(e22);
    cudaStreamDestroy(s1); cudaStreamDestroy(s2); cudaStreamDestroy(s3);
}